// round 9
// baseline (speedup 1.0000x reference)
#include <cuda_runtime.h>
#include <cuda_fp16.h>
#include <cstdint>

#define NT    16384
#define HD    1024
#define MD    512
#define NEXP  8

#define BM    128
#define BN    128
#define BK    32
#define NITER (HD / BK)       // 32
#define LDS   40              // smem row stride in halves (32 + 8 pad)
#define STG_BYTES (BM * LDS * 2)  // 10240 per stage per tile

// ---------------------------------------------------------------------------
// Static device scratch
// ---------------------------------------------------------------------------
__device__ float  g_h[NT * MD];                    // router hidden (fp32)
__device__ __half g_xh[NT * HD];                   // X in fp16
__device__ __half g_w1t[MD * HD];                  // w1^T [n][k] fp16
__device__ __half g_wt[NEXP * HD * HD];            // W^T  [e][n][k] fp16
__device__ int g_eid[NT], g_sorted[NT], g_cnt[NEXP], g_cur[NEXP];

// ---------------------------------------------------------------------------
// PTX helpers (compute_103 baseline: cp.async / ldmatrix / mma.sync)
// ---------------------------------------------------------------------------
__device__ __forceinline__ uint32_t smem_u32(const void* p) {
    uint32_t a;
    asm("{ .reg .u64 t; cvta.to.shared.u64 t, %1; cvt.u32.u64 %0, t; }" : "=r"(a) : "l"(p));
    return a;
}
#define CP16(sm, gm) \
    asm volatile("cp.async.cg.shared.global [%0], [%1], 16;" :: "r"(sm), "l"(gm))
#define CP_COMMIT() asm volatile("cp.async.commit_group;")
#define CP_WAIT1()  asm volatile("cp.async.wait_group 1;")
#define CP_WAIT0()  asm volatile("cp.async.wait_group 0;")

#define LDM4(r, a) \
    asm volatile("ldmatrix.sync.aligned.m8n8.x4.shared.b16 {%0,%1,%2,%3}, [%4];" \
        : "=r"((r)[0]), "=r"((r)[1]), "=r"((r)[2]), "=r"((r)[3]) : "r"(a))

#define MMA16816(d, a, b0, b1) \
    asm volatile("mma.sync.aligned.m16n8k16.row.col.f32.f16.f16.f32 " \
        "{%0,%1,%2,%3}, {%4,%5,%6,%7}, {%8,%9}, {%0,%1,%2,%3};" \
        : "+f"((d)[0]), "+f"((d)[1]), "+f"((d)[2]), "+f"((d)[3]) \
        : "r"((a)[0]), "r"((a)[1]), "r"((a)[2]), "r"((a)[3]), "r"(b0), "r"(b1))

// ---------------------------------------------------------------------------
// Launch 1: X fp32 -> fp16 (+ zero counters in block 0)
// ---------------------------------------------------------------------------
__global__ __launch_bounds__(256) void convx_kernel(const float* __restrict__ X) {
    if (blockIdx.x == 0 && threadIdx.x < NEXP) {
        g_cnt[threadIdx.x] = 0;
        g_cur[threadIdx.x] = 0;
    }
    size_t base = ((size_t)blockIdx.x * 256 + threadIdx.x) * 8;
    float4 v0 = *(const float4*)(X + base);
    float4 v1 = *(const float4*)(X + base + 4);
    __half2* d = (__half2*)(g_xh + base);
    d[0] = __floats2half2_rn(v0.x, v0.y);
    d[1] = __floats2half2_rn(v0.z, v0.w);
    d[2] = __floats2half2_rn(v1.x, v1.y);
    d[3] = __floats2half2_rn(v1.z, v1.w);
}

// Launch 2: weights fp32 [z][HD][ncols] -> fp16 transposed [z][n][HD]
// z = 0: w1 (ncols=MD) -> g_w1t ; z = 1..8: expert z-1 (ncols=HD) -> g_wt
__global__ __launch_bounds__(256) void transconv_kernel(
    const float* __restrict__ w1, const float* __restrict__ eW)
{
    __shared__ float t[32][33];
    int z = blockIdx.z;
    int ncols = (z == 0) ? MD : HD;
    int nb = blockIdx.x * 32, kb = blockIdx.y * 32;
    if (nb >= ncols) return;
    const float* S;
    __half* D;
    if (z == 0) { S = w1; D = g_w1t; }
    else { S = eW + (size_t)(z - 1) * HD * HD; D = g_wt + (size_t)(z - 1) * HD * HD; }
    int lx = threadIdx.x & 31, ly = threadIdx.x >> 5;
    #pragma unroll
    for (int i = 0; i < 4; i++)
        t[ly + i * 8][lx] = S[(size_t)(kb + ly + i * 8) * ncols + nb + lx];
    __syncthreads();
    #pragma unroll
    for (int i = 0; i < 4; i++) {
        int n = nb + ly + i * 8, k = kb + lx;
        D[(size_t)n * HD + k] = __float2half_rn(t[lx][ly + i * 8]);
    }
}

// ---------------------------------------------------------------------------
// fp16 mma.sync GEMM (R8-proven, unchanged): 128x128x32 CTA tile, 4 warps x
// (64x64) warp tiles, 128 threads, 2-stage cp.async, 2 CTAs/SM.
// ---------------------------------------------------------------------------
template<bool GATHER, bool RELU>
__global__ __launch_bounds__(128) void mma_gemm_kernel(
    const __half* __restrict__ Ag, const __half* __restrict__ Bg,
    const float* __restrict__ bias, float* __restrict__ out,
    int ostride, int npe)
{
    __shared__ __align__(16) __half As[2][BM * LDS];
    __shared__ __align__(16) __half Bs[2][BN * LDS];
    __shared__ int tokS[BM];

    int tid = threadIdx.x, lane = tid & 31, wid = tid >> 5;
    int e = blockIdx.y;
    int tile0 = blockIdx.z * BM;
    int n0 = blockIdx.x * BN;

    int cnt = NT;
    if (GATHER) {
        cnt = g_cnt[e];
        if (tile0 >= cnt) return;
        int seg = 0;
        #pragma unroll
        for (int i = 0; i < NEXP; i++) if (i < e) seg += g_cnt[i];
        tokS[tid] = g_sorted[seg + min(tile0 + tid, cnt - 1)];
        __syncthreads();
    }

    // Loader mapping: 4 x 16B pieces per tile per thread (128 rows x 64B)
    const __half* gA[4];
    const __half* gB[4];
    uint32_t sA[4], sB[4];
    const __half* Bbase = Bg + (size_t)e * npe * HD;
    uint32_t sAbase = smem_u32(As), sBbase = smem_u32(Bs);
    #pragma unroll
    for (int l = 0; l < 4; l++) {
        int idx = tid + l * 128;
        int r = idx >> 2, c = idx & 3;
        int arow = GATHER ? tokS[r] : (tile0 + r);
        gA[l] = Ag + (size_t)arow * HD + c * 8;
        gB[l] = Bbase + (size_t)(n0 + r) * HD + c * 8;
        sA[l] = sAbase + (r * LDS + c * 8) * 2;
        sB[l] = sBbase + (r * LDS + c * 8) * 2;
    }

    // 4 warps: 2 along M x 2 along N, each owns 64x64
    int wm = wid & 1, wn = wid >> 1;
    uint32_t aLd = sAbase + ((wm * 64 + (lane & 15)) * LDS + ((lane >> 4) << 3)) * 2;
    uint32_t bLd = sBbase + ((wn * 64 + (lane & 7) + ((lane & 16) ? 8 : 0)) * LDS
                             + ((lane & 8) ? 8 : 0)) * 2;

    float acc[4][8][4];
    #pragma unroll
    for (int i = 0; i < 4; i++)
        #pragma unroll
        for (int j = 0; j < 8; j++)
            #pragma unroll
            for (int q = 0; q < 4; q++) acc[i][j][q] = 0.f;

    #pragma unroll
    for (int l = 0; l < 4; l++) { CP16(sA[l], gA[l]); CP16(sB[l], gB[l]); }
    CP_COMMIT();

    for (int cch = 0; cch < NITER; cch++) {
        int buf = cch & 1;
        if (cch + 1 < NITER) {
            int nb = (cch + 1) & 1;
            int koff = (cch + 1) * BK;
            uint32_t so = nb * STG_BYTES;
            #pragma unroll
            for (int l = 0; l < 4; l++) {
                CP16(sA[l] + so, gA[l] + koff);
                CP16(sB[l] + so, gB[l] + koff);
            }
            CP_COMMIT();
            CP_WAIT1();
        } else {
            CP_WAIT0();
        }
        __syncthreads();

        uint32_t aB = aLd + buf * STG_BYTES;
        uint32_t bB = bLd + buf * STG_BYTES;
        #pragma unroll
        for (int kk = 0; kk < BK; kk += 16) {
            uint32_t ar[4][4], br[4][4];
            #pragma unroll
            for (int mi = 0; mi < 4; mi++)
                LDM4(ar[mi], aB + (mi * 16 * LDS + kk) * 2);
            #pragma unroll
            for (int p = 0; p < 4; p++)
                LDM4(br[p], bB + (p * 16 * LDS + kk) * 2);
            #pragma unroll
            for (int mi = 0; mi < 4; mi++) {
                #pragma unroll
                for (int nj = 0; nj < 8; nj++) {
                    uint32_t b0 = br[nj >> 1][(nj & 1) * 2];
                    uint32_t b1 = br[nj >> 1][(nj & 1) * 2 + 1];
                    MMA16816(acc[mi][nj], ar[mi], b0, b1);
                }
            }
        }
        __syncthreads();
    }

    const float* bptr = bias + (size_t)e * npe;
    int qrow = lane >> 2, qcol = (lane & 3) * 2;
    #pragma unroll
    for (int mi = 0; mi < 4; mi++) {
        #pragma unroll
        for (int hf = 0; hf < 2; hf++) {
            int mrow = wm * 64 + mi * 16 + qrow + hf * 8;
            if ((tile0 + mrow) >= cnt) continue;
            int orow = GATHER ? tokS[mrow] : (tile0 + mrow);
            float* orp = out + (size_t)orow * ostride + n0;
            #pragma unroll
            for (int nj = 0; nj < 8; nj++) {
                int coln = wn * 64 + nj * 8 + qcol;
                float2 bv = *(const float2*)(bptr + n0 + coln);
                float2 ov;
                ov.x = acc[mi][nj][hf * 2 + 0] + bv.x;
                ov.y = acc[mi][nj][hf * 2 + 1] + bv.y;
                if (RELU) { ov.x = fmaxf(ov.x, 0.f); ov.y = fmaxf(ov.y, 0.f); }
                *(float2*)(orp + coln) = ov;
            }
        }
    }
}

// ---------------------------------------------------------------------------
// Launch 4 (profiled): routing — scores from g_h, argmax; near-ties
// recomputed exactly in fp32 (body unchanged from R8)
// ---------------------------------------------------------------------------
#define TAU 1e-2f
__global__ __launch_bounds__(256) void route_kernel(
    const float* __restrict__ X,  const float* __restrict__ w1,
    const float* __restrict__ b1, const float* __restrict__ w2,
    const float* __restrict__ b2)
{
    __shared__ float w2s[MD * NEXP];
    for (int i = threadIdx.x; i < MD * NEXP; i += 256) w2s[i] = w2[i];
    __syncthreads();

    int warp = threadIdx.x >> 5, lane = threadIdx.x & 31;
    int t = blockIdx.x * 8 + warp;
    const float* hrow = &g_h[(size_t)t * MD];

    float s[NEXP];
    #pragma unroll
    for (int e = 0; e < NEXP; e++) s[e] = 0.f;
    for (int m = lane; m < MD; m += 32) {
        float hv = hrow[m];
        #pragma unroll
        for (int e = 0; e < NEXP; e++) s[e] += hv * w2s[m * NEXP + e];
    }
    #pragma unroll
    for (int o = 16; o > 0; o >>= 1)
        #pragma unroll
        for (int e = 0; e < NEXP; e++)
            s[e] += __shfl_xor_sync(0xffffffff, s[e], o);

    int need = 0, best = 0;
    if (lane == 0) {
        float v1 = -1e30f, v2 = -1e30f;
        #pragma unroll
        for (int e = 0; e < NEXP; e++) {
            float v = s[e] + b2[e];
            if (v > v1) { v2 = v1; v1 = v; best = e; }
            else if (v > v2) v2 = v;
        }
        need = (v1 - v2 < TAU) ? 1 : 0;
    }
    need = __shfl_sync(0xffffffff, need, 0);

    if (need) {
        float hl[16];
        #pragma unroll
        for (int j = 0; j < 16; j++) hl[j] = b1[lane * 16 + j];
        const float* xr = &X[(size_t)t * HD];
        for (int k = 0; k < HD; k++) {
            float xv = xr[k];
            const float* wr = &w1[(size_t)k * MD + lane * 16];
            #pragma unroll
            for (int j = 0; j < 16; j++) hl[j] += xv * wr[j];
        }
        float sr[NEXP];
        #pragma unroll
        for (int e = 0; e < NEXP; e++) sr[e] = 0.f;
        #pragma unroll
        for (int j = 0; j < 16; j++) {
            float hv = fmaxf(hl[j], 0.f);
            const float* wc = &w2s[(lane * 16 + j) * NEXP];
            #pragma unroll
            for (int e = 0; e < NEXP; e++) sr[e] += hv * wc[e];
        }
        #pragma unroll
        for (int o = 16; o > 0; o >>= 1)
            #pragma unroll
            for (int e = 0; e < NEXP; e++)
                sr[e] += __shfl_xor_sync(0xffffffff, sr[e], o);
        if (lane == 0) {
            float bv = sr[0] + b2[0]; best = 0;
            #pragma unroll
            for (int e = 1; e < NEXP; e++) {
                float v = sr[e] + b2[e];
                if (v > bv) { bv = v; best = e; }
            }
        }
    }
    if (lane == 0) {
        g_eid[t] = best;
        atomicAdd(&g_cnt[best], 1);
    }
}

// ---------------------------------------------------------------------------
// Launch 5: scatter with inline 8-wide prefix (prefix kernel removed)
// ---------------------------------------------------------------------------
__global__ void scatter_kernel(int ntok) {
    int t = blockIdx.x * 256 + threadIdx.x;
    if (t >= ntok) return;
    int e = g_eid[t];
    int seg = 0;
    #pragma unroll
    for (int i = 0; i < NEXP; i++) if (i < e) seg += g_cnt[i];
    int pos = seg + atomicAdd(&g_cur[e], 1);
    g_sorted[pos] = t;
}

// ---------------------------------------------------------------------------
extern "C" void kernel_launch(void* const* d_in, const int* in_sizes, int n_in,
                              void* d_out, int out_size)
{
    const float* X  = (const float*)d_in[0];
    const float* w1 = (const float*)d_in[1];
    const float* b1 = (const float*)d_in[2];
    const float* w2 = (const float*)d_in[3];
    const float* b2 = (const float*)d_in[4];
    const float* eW = (const float*)d_in[5];
    const float* eb = (const float*)d_in[6];
    float* out = (float*)d_out;

    __half *xh, *w1t, *wt;
    float* hbuf;
    cudaGetSymbolAddress((void**)&xh,   g_xh);
    cudaGetSymbolAddress((void**)&w1t,  g_w1t);
    cudaGetSymbolAddress((void**)&wt,   g_wt);
    cudaGetSymbolAddress((void**)&hbuf, g_h);

    convx_kernel<<<NT * HD / 2048, 256>>>(X);                   // launch 1
    transconv_kernel<<<dim3(32, 32, 9), 256>>>(w1, eW);         // launch 2
    mma_gemm_kernel<false, true><<<dim3(MD / BN, 1, NT / BM), 128>>>(  // launch 3
        xh, w1t, b1, hbuf, MD, MD);
    route_kernel<<<NT / 8, 256>>>(X, w1, b1, w2, b2);           // launch 4 (ncu)
    scatter_kernel<<<(NT + 255) / 256, 256>>>(NT);              // launch 5
    mma_gemm_kernel<true, false><<<dim3(HD / BN, NEXP, NT / BM), 128>>>(  // launch 6
        xh, wt, eb, out, HD, HD);
}

// round 10
// speedup vs baseline: 2.3579x; 2.3579x over previous
#include <cuda_runtime.h>
#include <cuda_fp16.h>
#include <cstdint>

#define NT    16384
#define HD    1024
#define MD    512
#define NEXP  8

#define BM    128
#define BN    128
#define BK    32
#define NITER (HD / BK)       // 32
#define LDS   40              // smem row stride in halves (32 + 8 pad)
#define STG_BYTES (BM * LDS * 2)  // 10240 per stage per tile
#define REFG  512             // refine grid

// ---------------------------------------------------------------------------
// Static device scratch
// ---------------------------------------------------------------------------
__device__ float  g_h[NT * MD];                    // router hidden (fp32)
__device__ __half g_xh[NT * HD];                   // X in fp16
__device__ __half g_w1t[MD * HD];                  // w1^T [n][k] fp16
__device__ __half g_wt[NEXP * HD * HD];            // W^T  [e][n][k] fp16
__device__ int g_eid[NT], g_sorted[NT], g_cnt[NEXP], g_cur[NEXP];
__device__ int g_nrefine, g_rlist[NT];

// ---------------------------------------------------------------------------
// PTX helpers (compute_103 baseline: cp.async / ldmatrix / mma.sync)
// ---------------------------------------------------------------------------
__device__ __forceinline__ uint32_t smem_u32(const void* p) {
    uint32_t a;
    asm("{ .reg .u64 t; cvta.to.shared.u64 t, %1; cvt.u32.u64 %0, t; }" : "=r"(a) : "l"(p));
    return a;
}
#define CP16(sm, gm) \
    asm volatile("cp.async.cg.shared.global [%0], [%1], 16;" :: "r"(sm), "l"(gm))
#define CP_COMMIT() asm volatile("cp.async.commit_group;")
#define CP_WAIT1()  asm volatile("cp.async.wait_group 1;")
#define CP_WAIT0()  asm volatile("cp.async.wait_group 0;")

#define LDM4(r, a) \
    asm volatile("ldmatrix.sync.aligned.m8n8.x4.shared.b16 {%0,%1,%2,%3}, [%4];" \
        : "=r"((r)[0]), "=r"((r)[1]), "=r"((r)[2]), "=r"((r)[3]) : "r"(a))

#define MMA16816(d, a, b0, b1) \
    asm volatile("mma.sync.aligned.m16n8k16.row.col.f32.f16.f16.f32 " \
        "{%0,%1,%2,%3}, {%4,%5,%6,%7}, {%8,%9}, {%0,%1,%2,%3};" \
        : "+f"((d)[0]), "+f"((d)[1]), "+f"((d)[2]), "+f"((d)[3]) \
        : "r"((a)[0]), "r"((a)[1]), "r"((a)[2]), "r"((a)[3]), "r"(b0), "r"(b1))

// ---------------------------------------------------------------------------
// Launch 1: X fp32 -> fp16 (+ zero counters in block 0)
// ---------------------------------------------------------------------------
__global__ __launch_bounds__(256) void convx_kernel(const float* __restrict__ X) {
    if (blockIdx.x == 0 && threadIdx.x < NEXP + 1) {
        if (threadIdx.x < NEXP) { g_cnt[threadIdx.x] = 0; g_cur[threadIdx.x] = 0; }
        else g_nrefine = 0;
    }
    size_t base = ((size_t)blockIdx.x * 256 + threadIdx.x) * 8;
    float4 v0 = *(const float4*)(X + base);
    float4 v1 = *(const float4*)(X + base + 4);
    __half2* d = (__half2*)(g_xh + base);
    d[0] = __floats2half2_rn(v0.x, v0.y);
    d[1] = __floats2half2_rn(v0.z, v0.w);
    d[2] = __floats2half2_rn(v1.x, v1.y);
    d[3] = __floats2half2_rn(v1.z, v1.w);
}

// Launch 2: weights fp32 [z][HD][ncols] -> fp16 transposed [z][n][HD]
__global__ __launch_bounds__(256) void transconv_kernel(
    const float* __restrict__ w1, const float* __restrict__ eW)
{
    __shared__ float t[32][33];
    int z = blockIdx.z;
    int ncols = (z == 0) ? MD : HD;
    int nb = blockIdx.x * 32, kb = blockIdx.y * 32;
    if (nb >= ncols) return;
    const float* S;
    __half* D;
    if (z == 0) { S = w1; D = g_w1t; }
    else { S = eW + (size_t)(z - 1) * HD * HD; D = g_wt + (size_t)(z - 1) * HD * HD; }
    int lx = threadIdx.x & 31, ly = threadIdx.x >> 5;
    #pragma unroll
    for (int i = 0; i < 4; i++)
        t[ly + i * 8][lx] = S[(size_t)(kb + ly + i * 8) * ncols + nb + lx];
    __syncthreads();
    #pragma unroll
    for (int i = 0; i < 4; i++) {
        int n = nb + ly + i * 8, k = kb + lx;
        D[(size_t)n * HD + k] = __float2half_rn(t[lx][ly + i * 8]);
    }
}

// ---------------------------------------------------------------------------
// fp16 mma.sync GEMM (R8-proven, unchanged)
// ---------------------------------------------------------------------------
template<bool GATHER, bool RELU>
__global__ __launch_bounds__(128) void mma_gemm_kernel(
    const __half* __restrict__ Ag, const __half* __restrict__ Bg,
    const float* __restrict__ bias, float* __restrict__ out,
    int ostride, int npe)
{
    __shared__ __align__(16) __half As[2][BM * LDS];
    __shared__ __align__(16) __half Bs[2][BN * LDS];
    __shared__ int tokS[BM];

    int tid = threadIdx.x, lane = tid & 31, wid = tid >> 5;
    int e = blockIdx.y;
    int tile0 = blockIdx.z * BM;
    int n0 = blockIdx.x * BN;

    int cnt = NT;
    if (GATHER) {
        cnt = g_cnt[e];
        if (tile0 >= cnt) return;
        int seg = 0;
        #pragma unroll
        for (int i = 0; i < NEXP; i++) if (i < e) seg += g_cnt[i];
        tokS[tid] = g_sorted[seg + min(tile0 + tid, cnt - 1)];
        __syncthreads();
    }

    const __half* gA[4];
    const __half* gB[4];
    uint32_t sA[4], sB[4];
    const __half* Bbase = Bg + (size_t)e * npe * HD;
    uint32_t sAbase = smem_u32(As), sBbase = smem_u32(Bs);
    #pragma unroll
    for (int l = 0; l < 4; l++) {
        int idx = tid + l * 128;
        int r = idx >> 2, c = idx & 3;
        int arow = GATHER ? tokS[r] : (tile0 + r);
        gA[l] = Ag + (size_t)arow * HD + c * 8;
        gB[l] = Bbase + (size_t)(n0 + r) * HD + c * 8;
        sA[l] = sAbase + (r * LDS + c * 8) * 2;
        sB[l] = sBbase + (r * LDS + c * 8) * 2;
    }

    int wm = wid & 1, wn = wid >> 1;
    uint32_t aLd = sAbase + ((wm * 64 + (lane & 15)) * LDS + ((lane >> 4) << 3)) * 2;
    uint32_t bLd = sBbase + ((wn * 64 + (lane & 7) + ((lane & 16) ? 8 : 0)) * LDS
                             + ((lane & 8) ? 8 : 0)) * 2;

    float acc[4][8][4];
    #pragma unroll
    for (int i = 0; i < 4; i++)
        #pragma unroll
        for (int j = 0; j < 8; j++)
            #pragma unroll
            for (int q = 0; q < 4; q++) acc[i][j][q] = 0.f;

    #pragma unroll
    for (int l = 0; l < 4; l++) { CP16(sA[l], gA[l]); CP16(sB[l], gB[l]); }
    CP_COMMIT();

    for (int cch = 0; cch < NITER; cch++) {
        int buf = cch & 1;
        if (cch + 1 < NITER) {
            int nb = (cch + 1) & 1;
            int koff = (cch + 1) * BK;
            uint32_t so = nb * STG_BYTES;
            #pragma unroll
            for (int l = 0; l < 4; l++) {
                CP16(sA[l] + so, gA[l] + koff);
                CP16(sB[l] + so, gB[l] + koff);
            }
            CP_COMMIT();
            CP_WAIT1();
        } else {
            CP_WAIT0();
        }
        __syncthreads();

        uint32_t aB = aLd + buf * STG_BYTES;
        uint32_t bB = bLd + buf * STG_BYTES;
        #pragma unroll
        for (int kk = 0; kk < BK; kk += 16) {
            uint32_t ar[4][4], br[4][4];
            #pragma unroll
            for (int mi = 0; mi < 4; mi++)
                LDM4(ar[mi], aB + (mi * 16 * LDS + kk) * 2);
            #pragma unroll
            for (int p = 0; p < 4; p++)
                LDM4(br[p], bB + (p * 16 * LDS + kk) * 2);
            #pragma unroll
            for (int mi = 0; mi < 4; mi++) {
                #pragma unroll
                for (int nj = 0; nj < 8; nj++) {
                    uint32_t b0 = br[nj >> 1][(nj & 1) * 2];
                    uint32_t b1 = br[nj >> 1][(nj & 1) * 2 + 1];
                    MMA16816(acc[mi][nj], ar[mi], b0, b1);
                }
            }
        }
        __syncthreads();
    }

    const float* bptr = bias + (size_t)e * npe;
    int qrow = lane >> 2, qcol = (lane & 3) * 2;
    #pragma unroll
    for (int mi = 0; mi < 4; mi++) {
        #pragma unroll
        for (int hf = 0; hf < 2; hf++) {
            int mrow = wm * 64 + mi * 16 + qrow + hf * 8;
            if ((tile0 + mrow) >= cnt) continue;
            int orow = GATHER ? tokS[mrow] : (tile0 + mrow);
            float* orp = out + (size_t)orow * ostride + n0;
            #pragma unroll
            for (int nj = 0; nj < 8; nj++) {
                int coln = wn * 64 + nj * 8 + qcol;
                float2 bv = *(const float2*)(bptr + n0 + coln);
                float2 ov;
                ov.x = acc[mi][nj][hf * 2 + 0] + bv.x;
                ov.y = acc[mi][nj][hf * 2 + 1] + bv.y;
                if (RELU) { ov.x = fmaxf(ov.x, 0.f); ov.y = fmaxf(ov.y, 0.f); }
                *(float2*)(orp + coln) = ov;
            }
        }
    }
}

// ---------------------------------------------------------------------------
// Launch 4 (profiled): base scoring pass. Near-ties appended to g_rlist;
// refine happens in the dedicated block-parallel kernel below.
// ---------------------------------------------------------------------------
#define TAU 1e-2f
__global__ __launch_bounds__(256) void route_pass1(
    const float* __restrict__ w2, const float* __restrict__ b2)
{
    __shared__ float w2s[MD * NEXP];
    for (int i = threadIdx.x; i < MD * NEXP; i += 256) w2s[i] = w2[i];
    __syncthreads();

    int warp = threadIdx.x >> 5, lane = threadIdx.x & 31;
    int t = blockIdx.x * 8 + warp;
    const float* hrow = &g_h[(size_t)t * MD];

    float s[NEXP];
    #pragma unroll
    for (int e = 0; e < NEXP; e++) s[e] = 0.f;
    for (int m = lane; m < MD; m += 32) {
        float hv = hrow[m];
        #pragma unroll
        for (int e = 0; e < NEXP; e++) s[e] += hv * w2s[m * NEXP + e];
    }
    #pragma unroll
    for (int o = 16; o > 0; o >>= 1)
        #pragma unroll
        for (int e = 0; e < NEXP; e++)
            s[e] += __shfl_xor_sync(0xffffffff, s[e], o);

    if (lane == 0) {
        float v1 = -1e30f, v2 = -1e30f; int best = 0;
        #pragma unroll
        for (int e = 0; e < NEXP; e++) {
            float v = s[e] + b2[e];
            if (v > v1) { v2 = v1; v1 = v; best = e; }
            else if (v > v2) v2 = v;
        }
        g_eid[t] = best;                       // provisional for refine tokens
        if (v1 - v2 < TAU) {
            int idx = atomicAdd(&g_nrefine, 1);
            g_rlist[idx] = t;
        }
    }
}

// ---------------------------------------------------------------------------
// Launch 5: block-parallel exact refinement. 8 tokens per chunk; h computed
// with the SAME accumulation order as the old warp-serial path (bit-identical),
// then warp 0 replays the original scoring routine verbatim.
// ---------------------------------------------------------------------------
__global__ __launch_bounds__(256) void refine_kernel(
    const float* __restrict__ X,  const float* __restrict__ w1,
    const float* __restrict__ b1, const float* __restrict__ w2,
    const float* __restrict__ b2)
{
    __shared__ float buf[8 * HD];   // xs during k-loop, then hs + w2s
    int tid = threadIdx.x;
    int n = g_nrefine;

    for (int base = blockIdx.x * 8; base < n; base += REFG * 8) {
        int nt = min(8, n - base);
        __syncthreads();
        // stage x rows
        for (int tt = 0; tt < nt; tt++) {
            int t = g_rlist[base + tt];
            for (int k = tid; k < HD; k += 256)
                buf[tt * HD + k] = X[(size_t)t * HD + k];
        }
        __syncthreads();

        // h columns j0=tid, j1=tid+256 for all 8 tokens; ascending-k single
        // accumulator == bit-identical to the old refine path
        float acc0[8], acc1[8];
        float bv0 = b1[tid], bv1 = b1[tid + 256];
        #pragma unroll
        for (int tt = 0; tt < 8; tt++) { acc0[tt] = bv0; acc1[tt] = bv1; }
        #pragma unroll 4
        for (int k = 0; k < HD; k++) {
            float wv0 = w1[(size_t)k * MD + tid];
            float wv1 = w1[(size_t)k * MD + tid + 256];
            #pragma unroll
            for (int tt = 0; tt < 8; tt++) {
                float xv = buf[tt * HD + k];
                acc0[tt] += xv * wv0;
                acc1[tt] += xv * wv1;
            }
        }
        __syncthreads();
        // hs at buf[0 .. 8*512), w2 at buf[8*512 .. 8*512+4096)
        #pragma unroll
        for (int tt = 0; tt < 8; tt++) {
            buf[tt * MD + tid]       = acc0[tt];
            buf[tt * MD + tid + 256] = acc1[tt];
        }
        float* w2s = buf + 8 * MD;
        for (int i = tid; i < MD * NEXP; i += 256) w2s[i] = w2[i];
        __syncthreads();

        // warp 0: original scoring routine, verbatim structure
        if (tid < 32) {
            int lane = tid;
            for (int tt = 0; tt < nt; tt++) {
                int t = g_rlist[base + tt];
                float sr[NEXP];
                #pragma unroll
                for (int e = 0; e < NEXP; e++) sr[e] = 0.f;
                #pragma unroll
                for (int j = 0; j < 16; j++) {
                    float hv = fmaxf(buf[tt * MD + lane * 16 + j], 0.f);
                    const float* wc = &w2s[(lane * 16 + j) * NEXP];
                    #pragma unroll
                    for (int e = 0; e < NEXP; e++) sr[e] += hv * wc[e];
                }
                #pragma unroll
                for (int o = 16; o > 0; o >>= 1)
                    #pragma unroll
                    for (int e = 0; e < NEXP; e++)
                        sr[e] += __shfl_xor_sync(0xffffffff, sr[e], o);
                if (lane == 0) {
                    float bv = sr[0] + b2[0]; int best = 0;
                    #pragma unroll
                    for (int e = 1; e < NEXP; e++) {
                        float v = sr[e] + b2[e];
                        if (v > bv) { bv = v; best = e; }
                    }
                    g_eid[t] = best;
                }
            }
        }
    }
}

// ---------------------------------------------------------------------------
// Launch 6: count; Launch 7: scatter (inline 8-wide prefix)
// ---------------------------------------------------------------------------
__global__ void count_kernel(int ntok) {
    int t = blockIdx.x * 256 + threadIdx.x;
    if (t >= ntok) return;
    atomicAdd(&g_cnt[g_eid[t]], 1);
}
__global__ void scatter_kernel(int ntok) {
    int t = blockIdx.x * 256 + threadIdx.x;
    if (t >= ntok) return;
    int e = g_eid[t];
    int seg = 0;
    #pragma unroll
    for (int i = 0; i < NEXP; i++) if (i < e) seg += g_cnt[i];
    int pos = seg + atomicAdd(&g_cur[e], 1);
    g_sorted[pos] = t;
}

// ---------------------------------------------------------------------------
extern "C" void kernel_launch(void* const* d_in, const int* in_sizes, int n_in,
                              void* d_out, int out_size)
{
    const float* X  = (const float*)d_in[0];
    const float* w1 = (const float*)d_in[1];
    const float* b1 = (const float*)d_in[2];
    const float* w2 = (const float*)d_in[3];
    const float* b2 = (const float*)d_in[4];
    const float* eW = (const float*)d_in[5];
    const float* eb = (const float*)d_in[6];
    float* out = (float*)d_out;

    __half *xh, *w1t, *wt;
    float* hbuf;
    cudaGetSymbolAddress((void**)&xh,   g_xh);
    cudaGetSymbolAddress((void**)&w1t,  g_w1t);
    cudaGetSymbolAddress((void**)&wt,   g_wt);
    cudaGetSymbolAddress((void**)&hbuf, g_h);

    convx_kernel<<<NT * HD / 2048, 256>>>(X);                   // launch 1
    transconv_kernel<<<dim3(32, 32, 9), 256>>>(w1, eW);         // launch 2
    mma_gemm_kernel<false, true><<<dim3(MD / BN, 1, NT / BM), 128>>>(  // launch 3
        xh, w1t, b1, hbuf, MD, MD);
    route_pass1<<<NT / 8, 256>>>(w2, b2);                       // launch 4 (ncu)
    refine_kernel<<<REFG, 256>>>(X, w1, b1, w2, b2);            // launch 5
    count_kernel<<<NT / 256, 256>>>(NT);                        // launch 6
    scatter_kernel<<<NT / 256, 256>>>(NT);                      // launch 7
    mma_gemm_kernel<true, false><<<dim3(HD / BN, NEXP, NT / BM), 128>>>(  // launch 8
        xh, wt, eb, out, HD, HD);
}

// round 13
// speedup vs baseline: 2.5157x; 1.0669x over previous
#include <cuda_runtime.h>
#include <cuda_fp16.h>
#include <cstdint>

#define NT    16384
#define HD    1024
#define MD    512
#define NEXP  8

#define BM    128
#define BN    128
#define BK    64
#define NITER (HD / BK)       // 16
#define LDSK  72              // smem row stride in halves (64 + 8 pad)
#define STG   18432           // bytes per stage per tile (128*72*2)
#define SM_A  0
#define SM_B  (2 * STG)
#define SM_TOK (4 * STG)      // 73728
#define DYN_SMEM (SM_TOK + 512)
#define REFG  512             // refine grid

// ---------------------------------------------------------------------------
// Static device scratch
// ---------------------------------------------------------------------------
__device__ __half g_h16[NT * MD];                  // router hidden (fp16)
__device__ __half g_xh[NT * HD];                   // X in fp16
__device__ __half g_w1t[MD * HD];                  // w1^T [n][k] fp16
__device__ __half g_wt[NEXP * HD * HD];            // W^T  [e][n][k] fp16
__device__ int g_eid[NT], g_sorted[NT], g_cnt[NEXP], g_cur[NEXP];
__device__ int g_nrefine, g_rlist[NT];

// ---------------------------------------------------------------------------
// PTX helpers (compute_103 baseline: cp.async / ldmatrix / mma.sync)
// ---------------------------------------------------------------------------
__device__ __forceinline__ uint32_t smem_u32(const void* p) {
    uint32_t a;
    asm("{ .reg .u64 t; cvta.to.shared.u64 t, %1; cvt.u32.u64 %0, t; }" : "=r"(a) : "l"(p));
    return a;
}
#define CP16(sm, gm) \
    asm volatile("cp.async.cg.shared.global [%0], [%1], 16;" :: "r"(sm), "l"(gm))
#define CP_COMMIT() asm volatile("cp.async.commit_group;")
#define CP_WAIT1()  asm volatile("cp.async.wait_group 1;")
#define CP_WAIT0()  asm volatile("cp.async.wait_group 0;")

#define LDM4(r, a) \
    asm volatile("ldmatrix.sync.aligned.m8n8.x4.shared.b16 {%0,%1,%2,%3}, [%4];" \
        : "=r"((r)[0]), "=r"((r)[1]), "=r"((r)[2]), "=r"((r)[3]) : "r"(a))

#define MMA16816(d, a, b0, b1) \
    asm volatile("mma.sync.aligned.m16n8k16.row.col.f32.f16.f16.f32 " \
        "{%0,%1,%2,%3}, {%4,%5,%6,%7}, {%8,%9}, {%0,%1,%2,%3};" \
        : "+f"((d)[0]), "+f"((d)[1]), "+f"((d)[2]), "+f"((d)[3]) \
        : "r"((a)[0]), "r"((a)[1]), "r"((a)[2]), "r"((a)[3]), "r"(b0), "r"(b1))

// ---------------------------------------------------------------------------
// Launches 1+2: X fp32 -> fp16 in two halves (keeps gemm1 at profile slot 4)
// ---------------------------------------------------------------------------
__global__ __launch_bounds__(256) void convx_kernel(const float* __restrict__ X,
                                                    int blk0) {
    if (blk0 == 0 && blockIdx.x == 0 && threadIdx.x < NEXP + 1) {
        if (threadIdx.x < NEXP) { g_cnt[threadIdx.x] = 0; g_cur[threadIdx.x] = 0; }
        else g_nrefine = 0;
    }
    size_t base = ((size_t)(blk0 + blockIdx.x) * 256 + threadIdx.x) * 8;
    float4 v0 = *(const float4*)(X + base);
    float4 v1 = *(const float4*)(X + base + 4);
    __half2* d = (__half2*)(g_xh + base);
    d[0] = __floats2half2_rn(v0.x, v0.y);
    d[1] = __floats2half2_rn(v0.z, v0.w);
    d[2] = __floats2half2_rn(v1.x, v1.y);
    d[3] = __floats2half2_rn(v1.z, v1.w);
}

// Launch 3: weights fp32 [z][HD][ncols] -> fp16 transposed [z][n][HD]
__global__ __launch_bounds__(256) void transconv_kernel(
    const float* __restrict__ w1, const float* __restrict__ eW)
{
    __shared__ float t[32][33];
    int z = blockIdx.z;
    int ncols = (z == 0) ? MD : HD;
    int nb = blockIdx.x * 32, kb = blockIdx.y * 32;
    if (nb >= ncols) return;
    const float* S;
    __half* D;
    if (z == 0) { S = w1; D = g_w1t; }
    else { S = eW + (size_t)(z - 1) * HD * HD; D = g_wt + (size_t)(z - 1) * HD * HD; }
    int lx = threadIdx.x & 31, ly = threadIdx.x >> 5;
    #pragma unroll
    for (int i = 0; i < 4; i++)
        t[ly + i * 8][lx] = S[(size_t)(kb + ly + i * 8) * ncols + nb + lx];
    __syncthreads();
    #pragma unroll
    for (int i = 0; i < 4; i++) {
        int n = nb + ly + i * 8, k = kb + lx;
        D[(size_t)n * HD + k] = __float2half_rn(t[lx][ly + i * 8]);
    }
}

// ---------------------------------------------------------------------------
// fp16 mma.sync GEMM: 128x128x64 chunks, 4 warps x (64x64), 128 threads,
// 2-stage cp.async, double-buffered ldmatrix fragments (LDSM(kk+1) || MMA(kk)).
// ---------------------------------------------------------------------------
template<bool GATHER, bool RELU, bool OUTH>
__global__ __launch_bounds__(128, 2) void mma_gemm_kernel(
    const __half* __restrict__ Ag, const __half* __restrict__ Bg,
    const float* __restrict__ bias, void* __restrict__ outv,
    int ostride, int npe)
{
    extern __shared__ __align__(16) char smem[];
    int* tokS = (int*)(smem + SM_TOK);

    int tid = threadIdx.x, lane = tid & 31, wid = tid >> 5;
    int e = blockIdx.y;
    int tile0 = blockIdx.z * BM;
    int n0 = blockIdx.x * BN;

    int cnt = NT;
    if (GATHER) {
        cnt = g_cnt[e];
        if (tile0 >= cnt) return;
        int seg = 0;
        #pragma unroll
        for (int i = 0; i < NEXP; i++) if (i < e) seg += g_cnt[i];
        tokS[tid] = g_sorted[seg + min(tile0 + tid, cnt - 1)];
        __syncthreads();
    }

    // Loader: thread covers rows r+16*l (l=0..7), col piece c (16B)
    int r = tid >> 3, c = tid & 7;
    const __half* gA[8];
    #pragma unroll
    for (int l = 0; l < 8; l++) {
        int rr = r + 16 * l;
        int arow = GATHER ? tokS[rr] : (tile0 + rr);
        gA[l] = Ag + (size_t)arow * HD + c * 8;
    }
    const __half* gBb = Bg + (size_t)e * npe * HD + (size_t)(n0 + r) * HD + c * 8;
    uint32_t sAbase = smem_u32(smem) + SM_A;
    uint32_t sBbase = smem_u32(smem) + SM_B;
    uint32_t sAb = sAbase + (r * LDSK + c * 8) * 2;
    uint32_t sBb = sBbase + (r * LDSK + c * 8) * 2;

    // 4 warps: 2 along M x 2 along N, each owns 64x64
    int wm = wid & 1, wn = wid >> 1;
    uint32_t aLd = sAbase + ((wm * 64 + (lane & 15)) * LDSK + ((lane >> 4) << 3)) * 2;
    uint32_t bLd = sBbase + ((wn * 64 + (lane & 7) + ((lane & 16) ? 8 : 0)) * LDSK
                             + ((lane & 8) ? 8 : 0)) * 2;

    float acc[4][8][4];
    #pragma unroll
    for (int i = 0; i < 4; i++)
        #pragma unroll
        for (int j = 0; j < 8; j++)
            #pragma unroll
            for (int q = 0; q < 4; q++) acc[i][j][q] = 0.f;

    // prefetch stage 0
    #pragma unroll
    for (int l = 0; l < 8; l++) {
        CP16(sAb + l * (16 * LDSK * 2), gA[l]);
        CP16(sBb + l * (16 * LDSK * 2), gBb + (size_t)l * 16 * HD);
    }
    CP_COMMIT();

    for (int cch = 0; cch < NITER; cch++) {
        int buf = cch & 1;
        if (cch + 1 < NITER) {
            int nb = (cch + 1) & 1;
            int koff = (cch + 1) * BK;
            uint32_t so = nb * STG;
            #pragma unroll
            for (int l = 0; l < 8; l++) {
                CP16(sAb + l * (16 * LDSK * 2) + so, gA[l] + koff);
                CP16(sBb + l * (16 * LDSK * 2) + so, gBb + (size_t)l * 16 * HD + koff);
            }
            CP_COMMIT();
            CP_WAIT1();
        } else {
            CP_WAIT0();
        }
        __syncthreads();

        uint32_t aB = aLd + buf * STG;
        uint32_t bB = bLd + buf * STG;

        uint32_t ar[2][4][4], br[2][4][4];
        // load frags for kk-step 0
        #pragma unroll
        for (int mi = 0; mi < 4; mi++)
            LDM4(ar[0][mi], aB + (mi * 16 * LDSK) * 2);
        #pragma unroll
        for (int p = 0; p < 4; p++)
            LDM4(br[0][p], bB + (p * 16 * LDSK) * 2);

        #pragma unroll
        for (int k4 = 0; k4 < BK / 16; k4++) {
            int cur = k4 & 1;
            if (k4 + 1 < BK / 16) {
                int nx = cur ^ 1;
                int kk = (k4 + 1) * 16;
                #pragma unroll
                for (int mi = 0; mi < 4; mi++)
                    LDM4(ar[nx][mi], aB + (mi * 16 * LDSK + kk) * 2);
                #pragma unroll
                for (int p = 0; p < 4; p++)
                    LDM4(br[nx][p], bB + (p * 16 * LDSK + kk) * 2);
            }
            #pragma unroll
            for (int mi = 0; mi < 4; mi++) {
                #pragma unroll
                for (int nj = 0; nj < 8; nj++) {
                    uint32_t b0 = br[cur][nj >> 1][(nj & 1) * 2];
                    uint32_t b1 = br[cur][nj >> 1][(nj & 1) * 2 + 1];
                    MMA16816(acc[mi][nj], ar[cur][mi], b0, b1);
                }
            }
        }
        __syncthreads();
    }

    // Epilogue: bias add (+relu), fp32 or fp16 output, scatter rows
    const float* bptr = bias + (size_t)e * npe;
    int qrow = lane >> 2, qcol = (lane & 3) * 2;
    #pragma unroll
    for (int mi = 0; mi < 4; mi++) {
        #pragma unroll
        for (int hf = 0; hf < 2; hf++) {
            int mrow = wm * 64 + mi * 16 + qrow + hf * 8;
            if ((tile0 + mrow) >= cnt) continue;
            int orow = GATHER ? tokS[mrow] : (tile0 + mrow);
            #pragma unroll
            for (int nj = 0; nj < 8; nj++) {
                int coln = wn * 64 + nj * 8 + qcol;
                float2 bv = *(const float2*)(bptr + n0 + coln);
                float ox = acc[mi][nj][hf * 2 + 0] + bv.x;
                float oy = acc[mi][nj][hf * 2 + 1] + bv.y;
                if (RELU) { ox = fmaxf(ox, 0.f); oy = fmaxf(oy, 0.f); }
                if (OUTH) {
                    __half* orp = (__half*)outv + (size_t)orow * ostride + n0;
                    *(__half2*)(orp + coln) = __floats2half2_rn(ox, oy);
                } else {
                    float* orp = (float*)outv + (size_t)orow * ostride + n0;
                    *(float2*)(orp + coln) = make_float2(ox, oy);
                }
            }
        }
    }
}

// ---------------------------------------------------------------------------
// Launch 5: base scoring from fp16 h; near-ties appended to g_rlist
// ---------------------------------------------------------------------------
#define TAU 1e-2f
__global__ __launch_bounds__(256) void route_pass1(
    const float* __restrict__ w2, const float* __restrict__ b2)
{
    __shared__ float w2s[MD * NEXP];
    for (int i = threadIdx.x; i < MD * NEXP; i += 256) w2s[i] = w2[i];
    __syncthreads();

    int warp = threadIdx.x >> 5, lane = threadIdx.x & 31;
    int t = blockIdx.x * 8 + warp;
    const __half* hrow = &g_h16[(size_t)t * MD];

    float s[NEXP];
    #pragma unroll
    for (int e = 0; e < NEXP; e++) s[e] = 0.f;
    for (int m = lane; m < MD; m += 32) {
        float hv = __half2float(hrow[m]);
        #pragma unroll
        for (int e = 0; e < NEXP; e++) s[e] += hv * w2s[m * NEXP + e];
    }
    #pragma unroll
    for (int o = 16; o > 0; o >>= 1)
        #pragma unroll
        for (int e = 0; e < NEXP; e++)
            s[e] += __shfl_xor_sync(0xffffffff, s[e], o);

    if (lane == 0) {
        float v1 = -1e30f, v2 = -1e30f; int best = 0;
        #pragma unroll
        for (int e = 0; e < NEXP; e++) {
            float v = s[e] + b2[e];
            if (v > v1) { v2 = v1; v1 = v; best = e; }
            else if (v > v2) v2 = v;
        }
        g_eid[t] = best;
        if (v1 - v2 < TAU) {
            int idx = atomicAdd(&g_nrefine, 1);
            g_rlist[idx] = t;
        }
    }
}

// ---------------------------------------------------------------------------
// Launch 6: block-parallel exact fp32 refinement (R10-proven, unchanged)
// ---------------------------------------------------------------------------
__global__ __launch_bounds__(256) void refine_kernel(
    const float* __restrict__ X,  const float* __restrict__ w1,
    const float* __restrict__ b1, const float* __restrict__ w2,
    const float* __restrict__ b2)
{
    __shared__ float buf[8 * HD];
    int tid = threadIdx.x;
    int n = g_nrefine;

    for (int base = blockIdx.x * 8; base < n; base += REFG * 8) {
        int nt = min(8, n - base);
        __syncthreads();
        for (int tt = 0; tt < nt; tt++) {
            int t = g_rlist[base + tt];
            for (int k = tid; k < HD; k += 256)
                buf[tt * HD + k] = X[(size_t)t * HD + k];
        }
        __syncthreads();

        float acc0[8], acc1[8];
        float bv0 = b1[tid], bv1 = b1[tid + 256];
        #pragma unroll
        for (int tt = 0; tt < 8; tt++) { acc0[tt] = bv0; acc1[tt] = bv1; }
        #pragma unroll 4
        for (int k = 0; k < HD; k++) {
            float wv0 = w1[(size_t)k * MD + tid];
            float wv1 = w1[(size_t)k * MD + tid + 256];
            #pragma unroll
            for (int tt = 0; tt < 8; tt++) {
                float xv = buf[tt * HD + k];
                acc0[tt] += xv * wv0;
                acc1[tt] += xv * wv1;
            }
        }
        __syncthreads();
        #pragma unroll
        for (int tt = 0; tt < 8; tt++) {
            buf[tt * MD + tid]       = acc0[tt];
            buf[tt * MD + tid + 256] = acc1[tt];
        }
        float* w2s = buf + 8 * MD;
        for (int i = tid; i < MD * NEXP; i += 256) w2s[i] = w2[i];
        __syncthreads();

        if (tid < 32) {
            int lane = tid;
            for (int tt = 0; tt < nt; tt++) {
                int t = g_rlist[base + tt];
                float sr[NEXP];
                #pragma unroll
                for (int e = 0; e < NEXP; e++) sr[e] = 0.f;
                #pragma unroll
                for (int j = 0; j < 16; j++) {
                    float hv = fmaxf(buf[tt * MD + lane * 16 + j], 0.f);
                    const float* wc = &w2s[(lane * 16 + j) * NEXP];
                    #pragma unroll
                    for (int e = 0; e < NEXP; e++) sr[e] += hv * wc[e];
                }
                #pragma unroll
                for (int o = 16; o > 0; o >>= 1)
                    #pragma unroll
                    for (int e = 0; e < NEXP; e++)
                        sr[e] += __shfl_xor_sync(0xffffffff, sr[e], o);
                if (lane == 0) {
                    float bv = sr[0] + b2[0]; int best = 0;
                    #pragma unroll
                    for (int e = 1; e < NEXP; e++) {
                        float v = sr[e] + b2[e];
                        if (v > bv) { bv = v; best = e; }
                    }
                    g_eid[t] = best;
                }
            }
        }
    }
}

// ---------------------------------------------------------------------------
// Launches 7/8: count; scatter (inline 8-wide prefix)
// ---------------------------------------------------------------------------
__global__ void count_kernel(int ntok) {
    int t = blockIdx.x * 256 + threadIdx.x;
    if (t >= ntok) return;
    atomicAdd(&g_cnt[g_eid[t]], 1);
}
__global__ void scatter_kernel(int ntok) {
    int t = blockIdx.x * 256 + threadIdx.x;
    if (t >= ntok) return;
    int e = g_eid[t];
    int seg = 0;
    #pragma unroll
    for (int i = 0; i < NEXP; i++) if (i < e) seg += g_cnt[i];
    int pos = seg + atomicAdd(&g_cur[e], 1);
    g_sorted[pos] = t;
}

// ---------------------------------------------------------------------------
extern "C" void kernel_launch(void* const* d_in, const int* in_sizes, int n_in,
                              void* d_out, int out_size)
{
    const float* X  = (const float*)d_in[0];
    const float* w1 = (const float*)d_in[1];
    const float* b1 = (const float*)d_in[2];
    const float* w2 = (const float*)d_in[3];
    const float* b2 = (const float*)d_in[4];
    const float* eW = (const float*)d_in[5];
    const float* eb = (const float*)d_in[6];
    float* out = (float*)d_out;

    cudaFuncSetAttribute(mma_gemm_kernel<false, true, true>,
                         cudaFuncAttributeMaxDynamicSharedMemorySize, DYN_SMEM);
    cudaFuncSetAttribute(mma_gemm_kernel<true, false, false>,
                         cudaFuncAttributeMaxDynamicSharedMemorySize, DYN_SMEM);

    __half *xh, *w1t, *wt, *hbuf;
    cudaGetSymbolAddress((void**)&xh,   g_xh);
    cudaGetSymbolAddress((void**)&w1t,  g_w1t);
    cudaGetSymbolAddress((void**)&wt,   g_wt);
    cudaGetSymbolAddress((void**)&hbuf, g_h16);

    int halfgrid = NT * HD / 2048 / 2;                          // 4096
    convx_kernel<<<halfgrid, 256>>>(X, 0);                      // launch 1
    convx_kernel<<<halfgrid, 256>>>(X, halfgrid);               // launch 2
    transconv_kernel<<<dim3(32, 32, 9), 256>>>(w1, eW);         // launch 3
    mma_gemm_kernel<false, true, true>                          // launch 4 (ncu)
        <<<dim3(MD / BN, 1, NT / BM), 128, DYN_SMEM>>>(
        xh, w1t, b1, hbuf, MD, MD);
    route_pass1<<<NT / 8, 256>>>(w2, b2);                       // launch 5
    refine_kernel<<<REFG, 256>>>(X, w1, b1, w2, b2);            // launch 6
    count_kernel<<<NT / 256, 256>>>(NT);                        // launch 7
    scatter_kernel<<<NT / 256, 256>>>(NT);                      // launch 8
    mma_gemm_kernel<true, false, false>                         // launch 9
        <<<dim3(HD / BN, NEXP, NT / BM), 128, DYN_SMEM>>>(
        xh, wt, eb, out, HD, HD);
}

// round 14
// speedup vs baseline: 2.5537x; 1.0151x over previous
#include <cuda_runtime.h>
#include <cuda_fp16.h>
#include <cstdint>

#define NT    16384
#define HD    1024
#define MD    512
#define NEXP  8

#define BM    128
#define BN    128
#define BK    64
#define NITER (HD / BK)       // 16
#define NSTG  3
#define LDSK  72              // smem row stride in halves (64 + 8 pad)
#define STG   36864           // bytes per stage (A tile 18432 + B tile 18432)
#define STG_B 18432
#define SM_TOK (NSTG * STG)   // 110592
#define DYN_SMEM (SM_TOK + 512)
#define REFG  512             // refine grid

// ---------------------------------------------------------------------------
// Static device scratch
// ---------------------------------------------------------------------------
__device__ __half g_h16[NT * MD];                  // router hidden (fp16)
__device__ __half g_xh[NT * HD];                   // X in fp16
__device__ __half g_w1t[MD * HD];                  // w1^T [n][k] fp16
__device__ __half g_wt[NEXP * HD * HD];            // W^T  [e][n][k] fp16
__device__ int g_eid[NT], g_sorted[NT], g_cnt[NEXP], g_cur[NEXP];
__device__ int g_nrefine, g_rlist[NT];

// ---------------------------------------------------------------------------
// PTX helpers (compute_103 baseline: cp.async / ldmatrix / mma.sync)
// ---------------------------------------------------------------------------
__device__ __forceinline__ uint32_t smem_u32(const void* p) {
    uint32_t a;
    asm("{ .reg .u64 t; cvta.to.shared.u64 t, %1; cvt.u32.u64 %0, t; }" : "=r"(a) : "l"(p));
    return a;
}
#define CP16(sm, gm) \
    asm volatile("cp.async.cg.shared.global [%0], [%1], 16;" :: "r"(sm), "l"(gm))
#define CP_COMMIT() asm volatile("cp.async.commit_group;")
#define CP_WAIT1()  asm volatile("cp.async.wait_group 1;")

#define LDM4(r, a) \
    asm volatile("ldmatrix.sync.aligned.m8n8.x4.shared.b16 {%0,%1,%2,%3}, [%4];" \
        : "=r"((r)[0]), "=r"((r)[1]), "=r"((r)[2]), "=r"((r)[3]) : "r"(a))

#define MMA16816(d, a, b0, b1) \
    asm volatile("mma.sync.aligned.m16n8k16.row.col.f32.f16.f16.f32 " \
        "{%0,%1,%2,%3}, {%4,%5,%6,%7}, {%8,%9}, {%0,%1,%2,%3};" \
        : "+f"((d)[0]), "+f"((d)[1]), "+f"((d)[2]), "+f"((d)[3]) \
        : "r"((a)[0]), "r"((a)[1]), "r"((a)[2]), "r"((a)[3]), "r"(b0), "r"(b1))

// ---------------------------------------------------------------------------
// Launches 1+2: X fp32 -> fp16 in two halves (keeps gemm1 at profile slot 4)
// ---------------------------------------------------------------------------
__global__ __launch_bounds__(256) void convx_kernel(const float* __restrict__ X,
                                                    int blk0) {
    if (blk0 == 0 && blockIdx.x == 0 && threadIdx.x < NEXP + 1) {
        if (threadIdx.x < NEXP) { g_cnt[threadIdx.x] = 0; g_cur[threadIdx.x] = 0; }
        else g_nrefine = 0;
    }
    size_t base = ((size_t)(blk0 + blockIdx.x) * 256 + threadIdx.x) * 8;
    float4 v0 = *(const float4*)(X + base);
    float4 v1 = *(const float4*)(X + base + 4);
    __half2* d = (__half2*)(g_xh + base);
    d[0] = __floats2half2_rn(v0.x, v0.y);
    d[1] = __floats2half2_rn(v0.z, v0.w);
    d[2] = __floats2half2_rn(v1.x, v1.y);
    d[3] = __floats2half2_rn(v1.z, v1.w);
}

// Launch 3: weights fp32 [z][HD][ncols] -> fp16 transposed [z][n][HD]
__global__ __launch_bounds__(256) void transconv_kernel(
    const float* __restrict__ w1, const float* __restrict__ eW)
{
    __shared__ float t[32][33];
    int z = blockIdx.z;
    int ncols = (z == 0) ? MD : HD;
    int nb = blockIdx.x * 32, kb = blockIdx.y * 32;
    if (nb >= ncols) return;
    const float* S;
    __half* D;
    if (z == 0) { S = w1; D = g_w1t; }
    else { S = eW + (size_t)(z - 1) * HD * HD; D = g_wt + (size_t)(z - 1) * HD * HD; }
    int lx = threadIdx.x & 31, ly = threadIdx.x >> 5;
    #pragma unroll
    for (int i = 0; i < 4; i++)
        t[ly + i * 8][lx] = S[(size_t)(kb + ly + i * 8) * ncols + nb + lx];
    __syncthreads();
    #pragma unroll
    for (int i = 0; i < 4; i++) {
        int n = nb + ly + i * 8, k = kb + lx;
        D[(size_t)n * HD + k] = __float2half_rn(t[lx][ly + i * 8]);
    }
}

// ---------------------------------------------------------------------------
// fp16 mma.sync GEMM: 128x128x64 chunks, 4 warps x (64x64), 128 threads,
// 3-stage cp.async ring, ONE __syncthreads per chunk, double-buffered
// ldmatrix fragments (LDSM(kk+1) overlaps MMA(kk)).
// ---------------------------------------------------------------------------
template<bool GATHER, bool RELU, bool OUTH>
__global__ __launch_bounds__(128, 2) void mma_gemm_kernel(
    const __half* __restrict__ Ag, const __half* __restrict__ Bg,
    const float* __restrict__ bias, void* __restrict__ outv,
    int ostride, int npe)
{
    extern __shared__ __align__(16) char smem[];
    int* tokS = (int*)(smem + SM_TOK);

    int tid = threadIdx.x, lane = tid & 31, wid = tid >> 5;
    int e = blockIdx.y;
    int tile0 = blockIdx.z * BM;
    int n0 = blockIdx.x * BN;

    int cnt = NT;
    if (GATHER) {
        cnt = g_cnt[e];
        if (tile0 >= cnt) return;
        int seg = 0;
        #pragma unroll
        for (int i = 0; i < NEXP; i++) if (i < e) seg += g_cnt[i];
        tokS[tid] = g_sorted[seg + min(tile0 + tid, cnt - 1)];
        __syncthreads();
    }

    // Loader: thread covers rows r+16*l (l=0..7), col piece c (16B)
    int r = tid >> 3, c = tid & 7;
    const __half* gA[8];
    #pragma unroll
    for (int l = 0; l < 8; l++) {
        int rr = r + 16 * l;
        int arow = GATHER ? tokS[rr] : (tile0 + rr);
        gA[l] = Ag + (size_t)arow * HD + c * 8;
    }
    const __half* gBb = Bg + (size_t)e * npe * HD + (size_t)(n0 + r) * HD + c * 8;
    uint32_t sbase = smem_u32(smem);
    uint32_t sAb = sbase + (r * LDSK + c * 8) * 2;             // + stage*STG
    uint32_t sBb = sbase + STG_B + (r * LDSK + c * 8) * 2;     // + stage*STG

    // 4 warps: 2 along M x 2 along N, each owns 64x64
    int wm = wid & 1, wn = wid >> 1;
    uint32_t aLd = sbase + ((wm * 64 + (lane & 15)) * LDSK + ((lane >> 4) << 3)) * 2;
    uint32_t bLd = sbase + STG_B + ((wn * 64 + (lane & 7) + ((lane & 16) ? 8 : 0)) * LDSK
                             + ((lane & 8) ? 8 : 0)) * 2;

    float acc[4][8][4];
    #pragma unroll
    for (int i = 0; i < 4; i++)
        #pragma unroll
        for (int j = 0; j < 8; j++)
            #pragma unroll
            for (int q = 0; q < 4; q++) acc[i][j][q] = 0.f;

    // prologue: prefetch stages 0, 1
    #pragma unroll
    for (int s = 0; s < NSTG - 1; s++) {
        uint32_t so = s * STG;
        int ko = s * BK;
        #pragma unroll
        for (int l = 0; l < 8; l++) {
            CP16(sAb + l * (16 * LDSK * 2) + so, gA[l] + ko);
            CP16(sBb + l * (16 * LDSK * 2) + so, gBb + (size_t)l * 16 * HD + ko);
        }
        CP_COMMIT();
    }

    int buf = 0, pbuf = NSTG - 1;
    for (int cch = 0; cch < NITER; cch++) {
        CP_WAIT1();            // stage cch resident
        __syncthreads();       // (also frees slot pbuf: all warps done reading it)

        if (cch + NSTG - 1 < NITER) {
            uint32_t so = pbuf * STG;
            int ko = (cch + NSTG - 1) * BK;
            #pragma unroll
            for (int l = 0; l < 8; l++) {
                CP16(sAb + l * (16 * LDSK * 2) + so, gA[l] + ko);
                CP16(sBb + l * (16 * LDSK * 2) + so, gBb + (size_t)l * 16 * HD + ko);
            }
        }
        CP_COMMIT();

        uint32_t aB = aLd + buf * STG;
        uint32_t bB = bLd + buf * STG;

        uint32_t ar[2][4][4], br[2][4][4];
        #pragma unroll
        for (int mi = 0; mi < 4; mi++)
            LDM4(ar[0][mi], aB + (mi * 16 * LDSK) * 2);
        #pragma unroll
        for (int p = 0; p < 4; p++)
            LDM4(br[0][p], bB + (p * 16 * LDSK) * 2);

        #pragma unroll
        for (int k4 = 0; k4 < BK / 16; k4++) {
            int cur = k4 & 1;
            if (k4 + 1 < BK / 16) {
                int nx = cur ^ 1;
                int kk = (k4 + 1) * 16;
                #pragma unroll
                for (int mi = 0; mi < 4; mi++)
                    LDM4(ar[nx][mi], aB + (mi * 16 * LDSK + kk) * 2);
                #pragma unroll
                for (int p = 0; p < 4; p++)
                    LDM4(br[nx][p], bB + (p * 16 * LDSK + kk) * 2);
            }
            #pragma unroll
            for (int mi = 0; mi < 4; mi++) {
                #pragma unroll
                for (int nj = 0; nj < 8; nj++) {
                    uint32_t b0 = br[cur][nj >> 1][(nj & 1) * 2];
                    uint32_t b1 = br[cur][nj >> 1][(nj & 1) * 2 + 1];
                    MMA16816(acc[mi][nj], ar[cur][mi], b0, b1);
                }
            }
        }
        buf  = (buf  == NSTG - 1) ? 0 : buf + 1;
        pbuf = (pbuf == NSTG - 1) ? 0 : pbuf + 1;
    }

    // Epilogue: bias add (+relu), fp32 or fp16 output, scatter rows
    const float* bptr = bias + (size_t)e * npe;
    int qrow = lane >> 2, qcol = (lane & 3) * 2;
    #pragma unroll
    for (int mi = 0; mi < 4; mi++) {
        #pragma unroll
        for (int hf = 0; hf < 2; hf++) {
            int mrow = wm * 64 + mi * 16 + qrow + hf * 8;
            if ((tile0 + mrow) >= cnt) continue;
            int orow = GATHER ? tokS[mrow] : (tile0 + mrow);
            #pragma unroll
            for (int nj = 0; nj < 8; nj++) {
                int coln = wn * 64 + nj * 8 + qcol;
                float2 bv = *(const float2*)(bptr + n0 + coln);
                float ox = acc[mi][nj][hf * 2 + 0] + bv.x;
                float oy = acc[mi][nj][hf * 2 + 1] + bv.y;
                if (RELU) { ox = fmaxf(ox, 0.f); oy = fmaxf(oy, 0.f); }
                if (OUTH) {
                    __half* orp = (__half*)outv + (size_t)orow * ostride + n0;
                    *(__half2*)(orp + coln) = __floats2half2_rn(ox, oy);
                } else {
                    float* orp = (float*)outv + (size_t)orow * ostride + n0;
                    *(float2*)(orp + coln) = make_float2(ox, oy);
                }
            }
        }
    }
}

// ---------------------------------------------------------------------------
// Launch 5: base scoring from fp16 h; counts provisional argmax; near-ties
// appended to g_rlist (refine adjusts counts by delta)
// ---------------------------------------------------------------------------
#define TAU 1e-2f
__global__ __launch_bounds__(256) void route_pass1(
    const float* __restrict__ w2, const float* __restrict__ b2)
{
    __shared__ float w2s[MD * NEXP];
    for (int i = threadIdx.x; i < MD * NEXP; i += 256) w2s[i] = w2[i];
    __syncthreads();

    int warp = threadIdx.x >> 5, lane = threadIdx.x & 31;
    int t = blockIdx.x * 8 + warp;
    const __half* hrow = &g_h16[(size_t)t * MD];

    float s[NEXP];
    #pragma unroll
    for (int e = 0; e < NEXP; e++) s[e] = 0.f;
    for (int m = lane; m < MD; m += 32) {
        float hv = __half2float(hrow[m]);
        #pragma unroll
        for (int e = 0; e < NEXP; e++) s[e] += hv * w2s[m * NEXP + e];
    }
    #pragma unroll
    for (int o = 16; o > 0; o >>= 1)
        #pragma unroll
        for (int e = 0; e < NEXP; e++)
            s[e] += __shfl_xor_sync(0xffffffff, s[e], o);

    if (lane == 0) {
        float v1 = -1e30f, v2 = -1e30f; int best = 0;
        #pragma unroll
        for (int e = 0; e < NEXP; e++) {
            float v = s[e] + b2[e];
            if (v > v1) { v2 = v1; v1 = v; best = e; }
            else if (v > v2) v2 = v;
        }
        g_eid[t] = best;
        atomicAdd(&g_cnt[best], 1);
        if (v1 - v2 < TAU) {
            int idx = atomicAdd(&g_nrefine, 1);
            g_rlist[idx] = t;
        }
    }
}

// ---------------------------------------------------------------------------
// Launch 6: block-parallel exact fp32 refinement; updates counts by delta
// ---------------------------------------------------------------------------
__global__ __launch_bounds__(256) void refine_kernel(
    const float* __restrict__ X,  const float* __restrict__ w1,
    const float* __restrict__ b1, const float* __restrict__ w2,
    const float* __restrict__ b2)
{
    __shared__ float buf[8 * HD];
    int tid = threadIdx.x;
    int n = g_nrefine;

    for (int base = blockIdx.x * 8; base < n; base += REFG * 8) {
        int nt = min(8, n - base);
        __syncthreads();
        for (int tt = 0; tt < nt; tt++) {
            int t = g_rlist[base + tt];
            for (int k = tid; k < HD; k += 256)
                buf[tt * HD + k] = X[(size_t)t * HD + k];
        }
        __syncthreads();

        float acc0[8], acc1[8];
        float bv0 = b1[tid], bv1 = b1[tid + 256];
        #pragma unroll
        for (int tt = 0; tt < 8; tt++) { acc0[tt] = bv0; acc1[tt] = bv1; }
        #pragma unroll 4
        for (int k = 0; k < HD; k++) {
            float wv0 = w1[(size_t)k * MD + tid];
            float wv1 = w1[(size_t)k * MD + tid + 256];
            #pragma unroll
            for (int tt = 0; tt < 8; tt++) {
                float xv = buf[tt * HD + k];
                acc0[tt] += xv * wv0;
                acc1[tt] += xv * wv1;
            }
        }
        __syncthreads();
        #pragma unroll
        for (int tt = 0; tt < 8; tt++) {
            buf[tt * MD + tid]       = acc0[tt];
            buf[tt * MD + tid + 256] = acc1[tt];
        }
        float* w2s = buf + 8 * MD;
        for (int i = tid; i < MD * NEXP; i += 256) w2s[i] = w2[i];
        __syncthreads();

        if (tid < 32) {
            int lane = tid;
            for (int tt = 0; tt < nt; tt++) {
                int t = g_rlist[base + tt];
                float sr[NEXP];
                #pragma unroll
                for (int e = 0; e < NEXP; e++) sr[e] = 0.f;
                #pragma unroll
                for (int j = 0; j < 16; j++) {
                    float hv = fmaxf(buf[tt * MD + lane * 16 + j], 0.f);
                    const float* wc = &w2s[(lane * 16 + j) * NEXP];
                    #pragma unroll
                    for (int e = 0; e < NEXP; e++) sr[e] += hv * wc[e];
                }
                #pragma unroll
                for (int o = 16; o > 0; o >>= 1)
                    #pragma unroll
                    for (int e = 0; e < NEXP; e++)
                        sr[e] += __shfl_xor_sync(0xffffffff, sr[e], o);
                if (lane == 0) {
                    float bv = sr[0] + b2[0]; int best = 0;
                    #pragma unroll
                    for (int e = 1; e < NEXP; e++) {
                        float v = sr[e] + b2[e];
                        if (v > bv) { bv = v; best = e; }
                    }
                    int old = g_eid[t];
                    if (best != old) {
                        atomicSub(&g_cnt[old], 1);
                        atomicAdd(&g_cnt[best], 1);
                        g_eid[t] = best;
                    }
                }
            }
        }
    }
}

// ---------------------------------------------------------------------------
// Launch 7: scatter (inline 8-wide prefix from final counts)
// ---------------------------------------------------------------------------
__global__ void scatter_kernel(int ntok) {
    int t = blockIdx.x * 256 + threadIdx.x;
    if (t >= ntok) return;
    int e = g_eid[t];
    int seg = 0;
    #pragma unroll
    for (int i = 0; i < NEXP; i++) if (i < e) seg += g_cnt[i];
    int pos = seg + atomicAdd(&g_cur[e], 1);
    g_sorted[pos] = t;
}

// ---------------------------------------------------------------------------
extern "C" void kernel_launch(void* const* d_in, const int* in_sizes, int n_in,
                              void* d_out, int out_size)
{
    const float* X  = (const float*)d_in[0];
    const float* w1 = (const float*)d_in[1];
    const float* b1 = (const float*)d_in[2];
    const float* w2 = (const float*)d_in[3];
    const float* b2 = (const float*)d_in[4];
    const float* eW = (const float*)d_in[5];
    const float* eb = (const float*)d_in[6];
    float* out = (float*)d_out;

    cudaFuncSetAttribute(mma_gemm_kernel<false, true, true>,
                         cudaFuncAttributeMaxDynamicSharedMemorySize, DYN_SMEM);
    cudaFuncSetAttribute(mma_gemm_kernel<true, false, false>,
                         cudaFuncAttributeMaxDynamicSharedMemorySize, DYN_SMEM);

    __half *xh, *w1t, *wt, *hbuf;
    cudaGetSymbolAddress((void**)&xh,   g_xh);
    cudaGetSymbolAddress((void**)&w1t,  g_w1t);
    cudaGetSymbolAddress((void**)&wt,   g_wt);
    cudaGetSymbolAddress((void**)&hbuf, g_h16);

    int halfgrid = NT * HD / 2048 / 2;                          // 4096
    convx_kernel<<<halfgrid, 256>>>(X, 0);                      // launch 1
    convx_kernel<<<halfgrid, 256>>>(X, halfgrid);               // launch 2
    transconv_kernel<<<dim3(32, 32, 9), 256>>>(w1, eW);         // launch 3
    mma_gemm_kernel<false, true, true>                          // launch 4 (ncu)
        <<<dim3(MD / BN, 1, NT / BM), 128, DYN_SMEM>>>(
        xh, w1t, b1, hbuf, MD, MD);
    route_pass1<<<NT / 8, 256>>>(w2, b2);                       // launch 5
    refine_kernel<<<REFG, 256>>>(X, w1, b1, w2, b2);            // launch 6
    scatter_kernel<<<NT / 256, 256>>>(NT);                      // launch 7
    mma_gemm_kernel<true, false, false>                         // launch 8
        <<<dim3(HD / BN, NEXP, NT / BM), 128, DYN_SMEM>>>(
        xh, wt, eb, out, HD, HD);
}

// round 15
// speedup vs baseline: 2.6045x; 1.0199x over previous
#include <cuda_runtime.h>
#include <cuda_fp16.h>
#include <cstdint>

#define NT    16384
#define HD    1024
#define MD    512
#define NEXP  8

#define BM    128
#define BN    128
#define BK    64
#define NITER (HD / BK)       // 16
#define NSTG  3
#define LDSK  72              // smem row stride in halves (64 + 8 pad)
#define STG   36864           // bytes per stage (A tile 18432 + B tile 18432)
#define STG_B 18432
#define SM_TOK (NSTG * STG)   // 110592
#define DYN_SMEM (SM_TOK + 512)
#define REFG  512             // refine grid

// ---------------------------------------------------------------------------
// Static device scratch
// ---------------------------------------------------------------------------
__device__ __half g_h16[NT * MD];                  // router hidden (fp16)
__device__ __half g_xh[NT * HD];                   // X in fp16
__device__ __half g_w1t[MD * HD];                  // w1^T [n][k] fp16
__device__ __half g_wt[NEXP * HD * HD];            // W^T  [e][n][k] fp16
__device__ int g_eid[NT], g_sorted[NT], g_cnt[NEXP], g_cur[NEXP];
__device__ int g_nrefine, g_rlist[NT];

// ---------------------------------------------------------------------------
// PTX helpers (compute_103 baseline: cp.async / ldmatrix / mma.sync)
// ---------------------------------------------------------------------------
__device__ __forceinline__ uint32_t smem_u32(const void* p) {
    uint32_t a;
    asm("{ .reg .u64 t; cvta.to.shared.u64 t, %1; cvt.u32.u64 %0, t; }" : "=r"(a) : "l"(p));
    return a;
}
#define CP16(sm, gm) \
    asm volatile("cp.async.cg.shared.global [%0], [%1], 16;" :: "r"(sm), "l"(gm))
#define CP_COMMIT() asm volatile("cp.async.commit_group;")
#define CP_WAIT1()  asm volatile("cp.async.wait_group 1;")

#define LDM4(r, a) \
    asm volatile("ldmatrix.sync.aligned.m8n8.x4.shared.b16 {%0,%1,%2,%3}, [%4];" \
        : "=r"((r)[0]), "=r"((r)[1]), "=r"((r)[2]), "=r"((r)[3]) : "r"(a))

#define MMA16816(d, a, b0, b1) \
    asm volatile("mma.sync.aligned.m16n8k16.row.col.f32.f16.f16.f32 " \
        "{%0,%1,%2,%3}, {%4,%5,%6,%7}, {%8,%9}, {%0,%1,%2,%3};" \
        : "+f"((d)[0]), "+f"((d)[1]), "+f"((d)[2]), "+f"((d)[3]) \
        : "r"((a)[0]), "r"((a)[1]), "r"((a)[2]), "r"((a)[3]), "r"(b0), "r"(b1))

// ---------------------------------------------------------------------------
// Launch 1: unified prep — blocks [0,8192): X fp32->fp16 (+zero counters);
// blocks [8192,17408): weight transpose+convert (bodies unchanged)
// ---------------------------------------------------------------------------
__global__ __launch_bounds__(256) void prep_kernel(
    const float* __restrict__ X, const float* __restrict__ w1,
    const float* __restrict__ eW)
{
    __shared__ float t[32][33];
    int bid = blockIdx.x;
    if (bid < 8192) {
        if (bid == 0 && threadIdx.x < NEXP + 1) {
            if (threadIdx.x < NEXP) { g_cnt[threadIdx.x] = 0; g_cur[threadIdx.x] = 0; }
            else g_nrefine = 0;
        }
        size_t base = ((size_t)bid * 256 + threadIdx.x) * 8;
        float4 v0 = *(const float4*)(X + base);
        float4 v1 = *(const float4*)(X + base + 4);
        __half2* d = (__half2*)(g_xh + base);
        d[0] = __floats2half2_rn(v0.x, v0.y);
        d[1] = __floats2half2_rn(v0.z, v0.w);
        d[2] = __floats2half2_rn(v1.x, v1.y);
        d[3] = __floats2half2_rn(v1.z, v1.w);
    } else {
        int b = bid - 8192;
        int z = b >> 10;               // 0..8 (1024 blocks per z)
        int rb = b & 1023;
        int nb = (rb & 31) * 32, kb = (rb >> 5) * 32;
        int ncols = (z == 0) ? MD : HD;
        if (nb >= ncols) return;
        const float* S;
        __half* D;
        if (z == 0) { S = w1; D = g_w1t; }
        else { S = eW + (size_t)(z - 1) * HD * HD; D = g_wt + (size_t)(z - 1) * HD * HD; }
        int lx = threadIdx.x & 31, ly = threadIdx.x >> 5;
        #pragma unroll
        for (int i = 0; i < 4; i++)
            t[ly + i * 8][lx] = S[(size_t)(kb + ly + i * 8) * ncols + nb + lx];
        __syncthreads();
        #pragma unroll
        for (int i = 0; i < 4; i++) {
            int n = nb + ly + i * 8, k = kb + lx;
            D[(size_t)n * HD + k] = __float2half_rn(t[lx][ly + i * 8]);
        }
    }
}

// ---------------------------------------------------------------------------
// fp16 mma.sync GEMM (R14-proven, unchanged): 128x128x64 chunks, 4 warps x
// (64x64), 3-stage cp.async ring, one __syncthreads per chunk, frag dbl-buf.
// ---------------------------------------------------------------------------
template<bool GATHER, bool RELU, bool OUTH>
__global__ __launch_bounds__(128, 2) void mma_gemm_kernel(
    const __half* __restrict__ Ag, const __half* __restrict__ Bg,
    const float* __restrict__ bias, void* __restrict__ outv,
    int ostride, int npe)
{
    extern __shared__ __align__(16) char smem[];
    int* tokS = (int*)(smem + SM_TOK);

    int tid = threadIdx.x, lane = tid & 31, wid = tid >> 5;
    int e = blockIdx.y;
    int tile0 = blockIdx.z * BM;
    int n0 = blockIdx.x * BN;

    int cnt = NT;
    if (GATHER) {
        cnt = g_cnt[e];
        if (tile0 >= cnt) return;
        int seg = 0;
        #pragma unroll
        for (int i = 0; i < NEXP; i++) if (i < e) seg += g_cnt[i];
        tokS[tid] = g_sorted[seg + min(tile0 + tid, cnt - 1)];
        __syncthreads();
    }

    int r = tid >> 3, c = tid & 7;
    const __half* gA[8];
    #pragma unroll
    for (int l = 0; l < 8; l++) {
        int rr = r + 16 * l;
        int arow = GATHER ? tokS[rr] : (tile0 + rr);
        gA[l] = Ag + (size_t)arow * HD + c * 8;
    }
    const __half* gBb = Bg + (size_t)e * npe * HD + (size_t)(n0 + r) * HD + c * 8;
    uint32_t sbase = smem_u32(smem);
    uint32_t sAb = sbase + (r * LDSK + c * 8) * 2;
    uint32_t sBb = sbase + STG_B + (r * LDSK + c * 8) * 2;

    int wm = wid & 1, wn = wid >> 1;
    uint32_t aLd = sbase + ((wm * 64 + (lane & 15)) * LDSK + ((lane >> 4) << 3)) * 2;
    uint32_t bLd = sbase + STG_B + ((wn * 64 + (lane & 7) + ((lane & 16) ? 8 : 0)) * LDSK
                             + ((lane & 8) ? 8 : 0)) * 2;

    float acc[4][8][4];
    #pragma unroll
    for (int i = 0; i < 4; i++)
        #pragma unroll
        for (int j = 0; j < 8; j++)
            #pragma unroll
            for (int q = 0; q < 4; q++) acc[i][j][q] = 0.f;

    #pragma unroll
    for (int s = 0; s < NSTG - 1; s++) {
        uint32_t so = s * STG;
        int ko = s * BK;
        #pragma unroll
        for (int l = 0; l < 8; l++) {
            CP16(sAb + l * (16 * LDSK * 2) + so, gA[l] + ko);
            CP16(sBb + l * (16 * LDSK * 2) + so, gBb + (size_t)l * 16 * HD + ko);
        }
        CP_COMMIT();
    }

    int buf = 0, pbuf = NSTG - 1;
    for (int cch = 0; cch < NITER; cch++) {
        CP_WAIT1();
        __syncthreads();

        if (cch + NSTG - 1 < NITER) {
            uint32_t so = pbuf * STG;
            int ko = (cch + NSTG - 1) * BK;
            #pragma unroll
            for (int l = 0; l < 8; l++) {
                CP16(sAb + l * (16 * LDSK * 2) + so, gA[l] + ko);
                CP16(sBb + l * (16 * LDSK * 2) + so, gBb + (size_t)l * 16 * HD + ko);
            }
        }
        CP_COMMIT();

        uint32_t aB = aLd + buf * STG;
        uint32_t bB = bLd + buf * STG;

        uint32_t ar[2][4][4], br[2][4][4];
        #pragma unroll
        for (int mi = 0; mi < 4; mi++)
            LDM4(ar[0][mi], aB + (mi * 16 * LDSK) * 2);
        #pragma unroll
        for (int p = 0; p < 4; p++)
            LDM4(br[0][p], bB + (p * 16 * LDSK) * 2);

        #pragma unroll
        for (int k4 = 0; k4 < BK / 16; k4++) {
            int cur = k4 & 1;
            if (k4 + 1 < BK / 16) {
                int nx = cur ^ 1;
                int kk = (k4 + 1) * 16;
                #pragma unroll
                for (int mi = 0; mi < 4; mi++)
                    LDM4(ar[nx][mi], aB + (mi * 16 * LDSK + kk) * 2);
                #pragma unroll
                for (int p = 0; p < 4; p++)
                    LDM4(br[nx][p], bB + (p * 16 * LDSK + kk) * 2);
            }
            #pragma unroll
            for (int mi = 0; mi < 4; mi++) {
                #pragma unroll
                for (int nj = 0; nj < 8; nj++) {
                    uint32_t b0 = br[cur][nj >> 1][(nj & 1) * 2];
                    uint32_t b1 = br[cur][nj >> 1][(nj & 1) * 2 + 1];
                    MMA16816(acc[mi][nj], ar[cur][mi], b0, b1);
                }
            }
        }
        buf  = (buf  == NSTG - 1) ? 0 : buf + 1;
        pbuf = (pbuf == NSTG - 1) ? 0 : pbuf + 1;
    }

    const float* bptr = bias + (size_t)e * npe;
    int qrow = lane >> 2, qcol = (lane & 3) * 2;
    #pragma unroll
    for (int mi = 0; mi < 4; mi++) {
        #pragma unroll
        for (int hf = 0; hf < 2; hf++) {
            int mrow = wm * 64 + mi * 16 + qrow + hf * 8;
            if ((tile0 + mrow) >= cnt) continue;
            int orow = GATHER ? tokS[mrow] : (tile0 + mrow);
            #pragma unroll
            for (int nj = 0; nj < 8; nj++) {
                int coln = wn * 64 + nj * 8 + qcol;
                float2 bv = *(const float2*)(bptr + n0 + coln);
                float ox = acc[mi][nj][hf * 2 + 0] + bv.x;
                float oy = acc[mi][nj][hf * 2 + 1] + bv.y;
                if (RELU) { ox = fmaxf(ox, 0.f); oy = fmaxf(oy, 0.f); }
                if (OUTH) {
                    __half* orp = (__half*)outv + (size_t)orow * ostride + n0;
                    *(__half2*)(orp + coln) = __floats2half2_rn(ox, oy);
                } else {
                    float* orp = (float*)outv + (size_t)orow * ostride + n0;
                    *(float2*)(orp + coln) = make_float2(ox, oy);
                }
            }
        }
    }
}

// ---------------------------------------------------------------------------
// Launch 3: base scoring from fp16 h. w2 staged TRANSPOSED [e][m] in smem ->
// stride-1 conflict-free reads (was 8-way bank conflict). Same summation
// order -> bit-identical scores. Counts provisional argmax; ties to g_rlist.
// ---------------------------------------------------------------------------
#define TAU 1e-2f
__global__ __launch_bounds__(256) void route_pass1(
    const float* __restrict__ w2, const float* __restrict__ b2)
{
    __shared__ float w2s[NEXP * MD];
    for (int i = threadIdx.x; i < MD * NEXP; i += 256) {
        int m = i >> 3, e = i & 7;
        w2s[e * MD + m] = w2[i];
    }
    __syncthreads();

    int warp = threadIdx.x >> 5, lane = threadIdx.x & 31;
    int t = blockIdx.x * 8 + warp;
    const __half* hrow = &g_h16[(size_t)t * MD];

    float s[NEXP];
    #pragma unroll
    for (int e = 0; e < NEXP; e++) s[e] = 0.f;
    for (int m = lane; m < MD; m += 32) {
        float hv = __half2float(hrow[m]);
        #pragma unroll
        for (int e = 0; e < NEXP; e++) s[e] += hv * w2s[e * MD + m];
    }
    #pragma unroll
    for (int o = 16; o > 0; o >>= 1)
        #pragma unroll
        for (int e = 0; e < NEXP; e++)
            s[e] += __shfl_xor_sync(0xffffffff, s[e], o);

    if (lane == 0) {
        float v1 = -1e30f, v2 = -1e30f; int best = 0;
        #pragma unroll
        for (int e = 0; e < NEXP; e++) {
            float v = s[e] + b2[e];
            if (v > v1) { v2 = v1; v1 = v; best = e; }
            else if (v > v2) v2 = v;
        }
        g_eid[t] = best;
        atomicAdd(&g_cnt[best], 1);
        if (v1 - v2 < TAU) {
            int idx = atomicAdd(&g_nrefine, 1);
            g_rlist[idx] = t;
        }
    }
}

// ---------------------------------------------------------------------------
// Launch 4 (profiled): block-parallel exact fp32 refinement; count deltas
// ---------------------------------------------------------------------------
__global__ __launch_bounds__(256) void refine_kernel(
    const float* __restrict__ X,  const float* __restrict__ w1,
    const float* __restrict__ b1, const float* __restrict__ w2,
    const float* __restrict__ b2)
{
    __shared__ float buf[8 * HD];
    int tid = threadIdx.x;
    int n = g_nrefine;

    for (int base = blockIdx.x * 8; base < n; base += REFG * 8) {
        int nt = min(8, n - base);
        __syncthreads();
        for (int tt = 0; tt < nt; tt++) {
            int t = g_rlist[base + tt];
            for (int k = tid; k < HD; k += 256)
                buf[tt * HD + k] = X[(size_t)t * HD + k];
        }
        __syncthreads();

        float acc0[8], acc1[8];
        float bv0 = b1[tid], bv1 = b1[tid + 256];
        #pragma unroll
        for (int tt = 0; tt < 8; tt++) { acc0[tt] = bv0; acc1[tt] = bv1; }
        #pragma unroll 4
        for (int k = 0; k < HD; k++) {
            float wv0 = w1[(size_t)k * MD + tid];
            float wv1 = w1[(size_t)k * MD + tid + 256];
            #pragma unroll
            for (int tt = 0; tt < 8; tt++) {
                float xv = buf[tt * HD + k];
                acc0[tt] += xv * wv0;
                acc1[tt] += xv * wv1;
            }
        }
        __syncthreads();
        #pragma unroll
        for (int tt = 0; tt < 8; tt++) {
            buf[tt * MD + tid]       = acc0[tt];
            buf[tt * MD + tid + 256] = acc1[tt];
        }
        float* w2s = buf + 8 * MD;
        for (int i = tid; i < MD * NEXP; i += 256) w2s[i] = w2[i];
        __syncthreads();

        if (tid < 32) {
            int lane = tid;
            for (int tt = 0; tt < nt; tt++) {
                int t = g_rlist[base + tt];
                float sr[NEXP];
                #pragma unroll
                for (int e = 0; e < NEXP; e++) sr[e] = 0.f;
                #pragma unroll
                for (int j = 0; j < 16; j++) {
                    float hv = fmaxf(buf[tt * MD + lane * 16 + j], 0.f);
                    const float* wc = &w2s[(lane * 16 + j) * NEXP];
                    #pragma unroll
                    for (int e = 0; e < NEXP; e++) sr[e] += hv * wc[e];
                }
                #pragma unroll
                for (int o = 16; o > 0; o >>= 1)
                    #pragma unroll
                    for (int e = 0; e < NEXP; e++)
                        sr[e] += __shfl_xor_sync(0xffffffff, sr[e], o);
                if (lane == 0) {
                    float bv = sr[0] + b2[0]; int best = 0;
                    #pragma unroll
                    for (int e = 1; e < NEXP; e++) {
                        float v = sr[e] + b2[e];
                        if (v > bv) { bv = v; best = e; }
                    }
                    int old = g_eid[t];
                    if (best != old) {
                        atomicSub(&g_cnt[old], 1);
                        atomicAdd(&g_cnt[best], 1);
                        g_eid[t] = best;
                    }
                }
            }
        }
    }
}

// ---------------------------------------------------------------------------
// Launch 5: scatter (inline 8-wide prefix from final counts)
// ---------------------------------------------------------------------------
__global__ void scatter_kernel(int ntok) {
    int t = blockIdx.x * 256 + threadIdx.x;
    if (t >= ntok) return;
    int e = g_eid[t];
    int seg = 0;
    #pragma unroll
    for (int i = 0; i < NEXP; i++) if (i < e) seg += g_cnt[i];
    int pos = seg + atomicAdd(&g_cur[e], 1);
    g_sorted[pos] = t;
}

// ---------------------------------------------------------------------------
extern "C" void kernel_launch(void* const* d_in, const int* in_sizes, int n_in,
                              void* d_out, int out_size)
{
    const float* X  = (const float*)d_in[0];
    const float* w1 = (const float*)d_in[1];
    const float* b1 = (const float*)d_in[2];
    const float* w2 = (const float*)d_in[3];
    const float* b2 = (const float*)d_in[4];
    const float* eW = (const float*)d_in[5];
    const float* eb = (const float*)d_in[6];
    float* out = (float*)d_out;

    cudaFuncSetAttribute(mma_gemm_kernel<false, true, true>,
                         cudaFuncAttributeMaxDynamicSharedMemorySize, DYN_SMEM);
    cudaFuncSetAttribute(mma_gemm_kernel<true, false, false>,
                         cudaFuncAttributeMaxDynamicSharedMemorySize, DYN_SMEM);

    __half *xh, *w1t, *wt, *hbuf;
    cudaGetSymbolAddress((void**)&xh,   g_xh);
    cudaGetSymbolAddress((void**)&w1t,  g_w1t);
    cudaGetSymbolAddress((void**)&wt,   g_wt);
    cudaGetSymbolAddress((void**)&hbuf, g_h16);

    prep_kernel<<<8192 + 9216, 256>>>(X, w1, eW);               // launch 1
    mma_gemm_kernel<false, true, true>                          // launch 2
        <<<dim3(MD / BN, 1, NT / BM), 128, DYN_SMEM>>>(
        xh, w1t, b1, hbuf, MD, MD);
    route_pass1<<<NT / 8, 256>>>(w2, b2);                       // launch 3
    refine_kernel<<<REFG, 256>>>(X, w1, b1, w2, b2);            // launch 4 (ncu)
    scatter_kernel<<<NT / 256, 256>>>(NT);                      // launch 5
    mma_gemm_kernel<true, false, false>                         // launch 6
        <<<dim3(HD / BN, NEXP, NT / BM), 128, DYN_SMEM>>>(
        xh, wt, eb, out, HD, HD);
}

// round 17
// speedup vs baseline: 2.7563x; 1.0583x over previous
#include <cuda_runtime.h>
#include <cuda_fp16.h>
#include <cstdint>

#define NT    16384
#define HD    1024
#define MD    512
#define NEXP  8

#define BM    128
#define BN    128
#define BK    64
#define NITER (HD / BK)       // 16
#define NSTG  3
#define LDSK  72              // smem row stride in halves (64 + 8 pad)
#define STG   36864           // bytes per stage (A tile 18432 + B tile 18432)
#define STG_B 18432
#define SM_TOK (NSTG * STG)   // 110592
#define DYN_SMEM (SM_TOK + 512)
#define NCHK  512             // refine chunks in flight (tokens/8)
#define REFG  (NCHK * 4)      // refine grid: 4 col-quarters per chunk

// ---------------------------------------------------------------------------
// Static device scratch
// ---------------------------------------------------------------------------
__device__ __half g_h16[NT * MD];                  // router hidden (fp16)
__device__ __half g_xh[NT * HD];                   // X in fp16
__device__ __half g_w1t[MD * HD];                  // w1^T [n][k] fp16
__device__ __half g_wt[NEXP * HD * HD];            // W^T  [e][n][k] fp16
__device__ float  g_rspart[NT * 32];               // refine partial scores [pos][q*8+e]
__device__ int g_eid[NT], g_sorted[NT], g_cnt[NEXP], g_cur[NEXP];
__device__ int g_nrefine, g_rlist[NT];

// ---------------------------------------------------------------------------
// PTX helpers (compute_103 baseline: cp.async / ldmatrix / mma.sync)
// ---------------------------------------------------------------------------
__device__ __forceinline__ uint32_t smem_u32(const void* p) {
    uint32_t a;
    asm("{ .reg .u64 t; cvta.to.shared.u64 t, %1; cvt.u32.u64 %0, t; }" : "=r"(a) : "l"(p));
    return a;
}
#define CP16(sm, gm) \
    asm volatile("cp.async.cg.shared.global [%0], [%1], 16;" :: "r"(sm), "l"(gm))
#define CP_COMMIT() asm volatile("cp.async.commit_group;")
#define CP_WAIT1()  asm volatile("cp.async.wait_group 1;")

#define LDM4(r, a) \
    asm volatile("ldmatrix.sync.aligned.m8n8.x4.shared.b16 {%0,%1,%2,%3}, [%4];" \
        : "=r"((r)[0]), "=r"((r)[1]), "=r"((r)[2]), "=r"((r)[3]) : "r"(a))

#define MMA16816(d, a, b0, b1) \
    asm volatile("mma.sync.aligned.m16n8k16.row.col.f32.f16.f16.f32 " \
        "{%0,%1,%2,%3}, {%4,%5,%6,%7}, {%8,%9}, {%0,%1,%2,%3};" \
        : "+f"((d)[0]), "+f"((d)[1]), "+f"((d)[2]), "+f"((d)[3]) \
        : "r"((a)[0]), "r"((a)[1]), "r"((a)[2]), "r"((a)[3]), "r"(b0), "r"(b1))

// ---------------------------------------------------------------------------
// Launch 1: unified prep — blocks [0,8192): X fp32->fp16 (+zero counters);
// blocks [8192,17408): weight transpose+convert
// ---------------------------------------------------------------------------
__global__ __launch_bounds__(256) void prep_kernel(
    const float* __restrict__ X, const float* __restrict__ w1,
    const float* __restrict__ eW)
{
    __shared__ float t[32][33];
    int bid = blockIdx.x;
    if (bid < 8192) {
        if (bid == 0 && threadIdx.x < NEXP + 1) {
            if (threadIdx.x < NEXP) { g_cnt[threadIdx.x] = 0; g_cur[threadIdx.x] = 0; }
            else g_nrefine = 0;
        }
        size_t base = ((size_t)bid * 256 + threadIdx.x) * 8;
        float4 v0 = *(const float4*)(X + base);
        float4 v1 = *(const float4*)(X + base + 4);
        __half2* d = (__half2*)(g_xh + base);
        d[0] = __floats2half2_rn(v0.x, v0.y);
        d[1] = __floats2half2_rn(v0.z, v0.w);
        d[2] = __floats2half2_rn(v1.x, v1.y);
        d[3] = __floats2half2_rn(v1.z, v1.w);
    } else {
        int b = bid - 8192;
        int z = b >> 10;
        int rb = b & 1023;
        int nb = (rb & 31) * 32, kb = (rb >> 5) * 32;
        int ncols = (z == 0) ? MD : HD;
        if (nb >= ncols) return;
        const float* S;
        __half* D;
        if (z == 0) { S = w1; D = g_w1t; }
        else { S = eW + (size_t)(z - 1) * HD * HD; D = g_wt + (size_t)(z - 1) * HD * HD; }
        int lx = threadIdx.x & 31, ly = threadIdx.x >> 5;
        #pragma unroll
        for (int i = 0; i < 4; i++)
            t[ly + i * 8][lx] = S[(size_t)(kb + ly + i * 8) * ncols + nb + lx];
        __syncthreads();
        #pragma unroll
        for (int i = 0; i < 4; i++) {
            int n = nb + ly + i * 8, k = kb + lx;
            D[(size_t)n * HD + k] = __float2half_rn(t[lx][ly + i * 8]);
        }
    }
}

// ---------------------------------------------------------------------------
// fp16 mma.sync GEMM (R14-proven, unchanged)
// ---------------------------------------------------------------------------
template<bool GATHER, bool RELU, bool OUTH>
__global__ __launch_bounds__(128, 2) void mma_gemm_kernel(
    const __half* __restrict__ Ag, const __half* __restrict__ Bg,
    const float* __restrict__ bias, void* __restrict__ outv,
    int ostride, int npe)
{
    extern __shared__ __align__(16) char smem[];
    int* tokS = (int*)(smem + SM_TOK);

    int tid = threadIdx.x, lane = tid & 31, wid = tid >> 5;
    int e = blockIdx.y;
    int tile0 = blockIdx.z * BM;
    int n0 = blockIdx.x * BN;

    int cnt = NT;
    if (GATHER) {
        cnt = g_cnt[e];
        if (tile0 >= cnt) return;
        int seg = 0;
        #pragma unroll
        for (int i = 0; i < NEXP; i++) if (i < e) seg += g_cnt[i];
        tokS[tid] = g_sorted[seg + min(tile0 + tid, cnt - 1)];
        __syncthreads();
    }

    int r = tid >> 3, c = tid & 7;
    const __half* gA[8];
    #pragma unroll
    for (int l = 0; l < 8; l++) {
        int rr = r + 16 * l;
        int arow = GATHER ? tokS[rr] : (tile0 + rr);
        gA[l] = Ag + (size_t)arow * HD + c * 8;
    }
    const __half* gBb = Bg + (size_t)e * npe * HD + (size_t)(n0 + r) * HD + c * 8;
    uint32_t sbase = smem_u32(smem);
    uint32_t sAb = sbase + (r * LDSK + c * 8) * 2;
    uint32_t sBb = sbase + STG_B + (r * LDSK + c * 8) * 2;

    int wm = wid & 1, wn = wid >> 1;
    uint32_t aLd = sbase + ((wm * 64 + (lane & 15)) * LDSK + ((lane >> 4) << 3)) * 2;
    uint32_t bLd = sbase + STG_B + ((wn * 64 + (lane & 7) + ((lane & 16) ? 8 : 0)) * LDSK
                             + ((lane & 8) ? 8 : 0)) * 2;

    float acc[4][8][4];
    #pragma unroll
    for (int i = 0; i < 4; i++)
        #pragma unroll
        for (int j = 0; j < 8; j++)
            #pragma unroll
            for (int q = 0; q < 4; q++) acc[i][j][q] = 0.f;

    #pragma unroll
    for (int s = 0; s < NSTG - 1; s++) {
        uint32_t so = s * STG;
        int ko = s * BK;
        #pragma unroll
        for (int l = 0; l < 8; l++) {
            CP16(sAb + l * (16 * LDSK * 2) + so, gA[l] + ko);
            CP16(sBb + l * (16 * LDSK * 2) + so, gBb + (size_t)l * 16 * HD + ko);
        }
        CP_COMMIT();
    }

    int buf = 0, pbuf = NSTG - 1;
    for (int cch = 0; cch < NITER; cch++) {
        CP_WAIT1();
        __syncthreads();

        if (cch + NSTG - 1 < NITER) {
            uint32_t so = pbuf * STG;
            int ko = (cch + NSTG - 1) * BK;
            #pragma unroll
            for (int l = 0; l < 8; l++) {
                CP16(sAb + l * (16 * LDSK * 2) + so, gA[l] + ko);
                CP16(sBb + l * (16 * LDSK * 2) + so, gBb + (size_t)l * 16 * HD + ko);
            }
        }
        CP_COMMIT();

        uint32_t aB = aLd + buf * STG;
        uint32_t bB = bLd + buf * STG;

        uint32_t ar[2][4][4], br[2][4][4];
        #pragma unroll
        for (int mi = 0; mi < 4; mi++)
            LDM4(ar[0][mi], aB + (mi * 16 * LDSK) * 2);
        #pragma unroll
        for (int p = 0; p < 4; p++)
            LDM4(br[0][p], bB + (p * 16 * LDSK) * 2);

        #pragma unroll
        for (int k4 = 0; k4 < BK / 16; k4++) {
            int cur = k4 & 1;
            if (k4 + 1 < BK / 16) {
                int nx = cur ^ 1;
                int kk = (k4 + 1) * 16;
                #pragma unroll
                for (int mi = 0; mi < 4; mi++)
                    LDM4(ar[nx][mi], aB + (mi * 16 * LDSK + kk) * 2);
                #pragma unroll
                for (int p = 0; p < 4; p++)
                    LDM4(br[nx][p], bB + (p * 16 * LDSK + kk) * 2);
            }
            #pragma unroll
            for (int mi = 0; mi < 4; mi++) {
                #pragma unroll
                for (int nj = 0; nj < 8; nj++) {
                    uint32_t b0 = br[cur][nj >> 1][(nj & 1) * 2];
                    uint32_t b1 = br[cur][nj >> 1][(nj & 1) * 2 + 1];
                    MMA16816(acc[mi][nj], ar[cur][mi], b0, b1);
                }
            }
        }
        buf  = (buf  == NSTG - 1) ? 0 : buf + 1;
        pbuf = (pbuf == NSTG - 1) ? 0 : pbuf + 1;
    }

    const float* bptr = bias + (size_t)e * npe;
    int qrow = lane >> 2, qcol = (lane & 3) * 2;
    #pragma unroll
    for (int mi = 0; mi < 4; mi++) {
        #pragma unroll
        for (int hf = 0; hf < 2; hf++) {
            int mrow = wm * 64 + mi * 16 + qrow + hf * 8;
            if ((tile0 + mrow) >= cnt) continue;
            int orow = GATHER ? tokS[mrow] : (tile0 + mrow);
            #pragma unroll
            for (int nj = 0; nj < 8; nj++) {
                int coln = wn * 64 + nj * 8 + qcol;
                float2 bv = *(const float2*)(bptr + n0 + coln);
                float ox = acc[mi][nj][hf * 2 + 0] + bv.x;
                float oy = acc[mi][nj][hf * 2 + 1] + bv.y;
                if (RELU) { ox = fmaxf(ox, 0.f); oy = fmaxf(oy, 0.f); }
                if (OUTH) {
                    __half* orp = (__half*)outv + (size_t)orow * ostride + n0;
                    *(__half2*)(orp + coln) = __floats2half2_rn(ox, oy);
                } else {
                    float* orp = (float*)outv + (size_t)orow * ostride + n0;
                    *(float2*)(orp + coln) = make_float2(ox, oy);
                }
            }
        }
    }
}

// ---------------------------------------------------------------------------
// Launch 3: base scoring (R15-proven, unchanged; w2 transposed in smem)
// ---------------------------------------------------------------------------
#define TAU 1e-2f
__global__ __launch_bounds__(256) void route_pass1(
    const float* __restrict__ w2, const float* __restrict__ b2)
{
    __shared__ float w2s[NEXP * MD];
    for (int i = threadIdx.x; i < MD * NEXP; i += 256) {
        int m = i >> 3, e = i & 7;
        w2s[e * MD + m] = w2[i];
    }
    __syncthreads();

    int warp = threadIdx.x >> 5, lane = threadIdx.x & 31;
    int t = blockIdx.x * 8 + warp;
    const __half* hrow = &g_h16[(size_t)t * MD];

    float s[NEXP];
    #pragma unroll
    for (int e = 0; e < NEXP; e++) s[e] = 0.f;
    for (int m = lane; m < MD; m += 32) {
        float hv = __half2float(hrow[m]);
        #pragma unroll
        for (int e = 0; e < NEXP; e++) s[e] += hv * w2s[e * MD + m];
    }
    #pragma unroll
    for (int o = 16; o > 0; o >>= 1)
        #pragma unroll
        for (int e = 0; e < NEXP; e++)
            s[e] += __shfl_xor_sync(0xffffffff, s[e], o);

    if (lane == 0) {
        float v1 = -1e30f, v2 = -1e30f; int best = 0;
        #pragma unroll
        for (int e = 0; e < NEXP; e++) {
            float v = s[e] + b2[e];
            if (v > v1) { v2 = v1; v1 = v; best = e; }
            else if (v > v2) v2 = v;
        }
        g_eid[t] = best;
        atomicAdd(&g_cnt[best], 1);
        if (v1 - v2 < TAU) {
            int idx = atomicAdd(&g_nrefine, 1);
            g_rlist[idx] = t;
        }
    }
}

// ---------------------------------------------------------------------------
// Launch 4 (profiled): refine v2 — (chunk, col-quarter) blocks. Each block:
// 8 tokens x 128 h-cols exact fp32, partial scores -> g_rspart (fixed slots).
// ---------------------------------------------------------------------------
__global__ __launch_bounds__(256) void refine_kernel(
    const float* __restrict__ X,  const float* __restrict__ w1,
    const float* __restrict__ b1, const float* __restrict__ w2)
{
    __shared__ float xs[8 * HD];       // 32 KB
    __shared__ float hs[8 * 128];      // 4 KB
    __shared__ float w2s[NEXP * 128];  // 4 KB, transposed [e][col]
    int tid = threadIdx.x;
    int n = g_nrefine;
    int q = blockIdx.x & 3;
    int c0 = q * 128;

    for (int chunk = blockIdx.x >> 2; chunk * 8 < n; chunk += NCHK) {
        int base = chunk * 8;
        int nt = min(8, n - base);
        __syncthreads();
        // stage x rows (full k range)
        for (int tt = 0; tt < nt; tt++) {
            int t = g_rlist[base + tt];
            for (int k = tid; k < HD; k += 256)
                xs[tt * HD + k] = X[(size_t)t * HD + k];
        }
        // stage w2 quarter transposed
        for (int i = tid; i < 128 * NEXP; i += 256) {
            int cc = i >> 3, e = i & 7;
            w2s[e * 128 + cc] = w2[(size_t)(c0 + cc) * NEXP + e];
        }
        __syncthreads();

        // h for 4 tokens x 1 col per thread (group g covers tokens g*4..g*4+3)
        int g = tid >> 7, c = tid & 127;
        int jcol = c0 + c;
        float a0 = b1[jcol], a1 = a0, a2 = a0, a3 = a0;
        const float* wp = w1 + jcol;
        const float* x0 = xs + (g * 4 + 0) * HD;
        const float* x1 = xs + (g * 4 + 1) * HD;
        const float* x2 = xs + (g * 4 + 2) * HD;
        const float* x3 = xs + (g * 4 + 3) * HD;
        #pragma unroll 8
        for (int k = 0; k < HD; k++) {
            float wv = wp[(size_t)k * MD];
            a0 += x0[k] * wv;
            a1 += x1[k] * wv;
            a2 += x2[k] * wv;
            a3 += x3[k] * wv;
        }
        hs[(g * 4 + 0) * 128 + c] = a0;
        hs[(g * 4 + 1) * 128 + c] = a1;
        hs[(g * 4 + 2) * 128 + c] = a2;
        hs[(g * 4 + 3) * 128 + c] = a3;
        __syncthreads();

        // partial scores: warp w handles token w
        int wid2 = tid >> 5, lane = tid & 31;
        if (wid2 < nt) {
            float s[NEXP];
            #pragma unroll
            for (int e = 0; e < NEXP; e++) s[e] = 0.f;
            #pragma unroll
            for (int i = 0; i < 4; i++) {
                int cc = lane + i * 32;
                float hv = fmaxf(hs[wid2 * 128 + cc], 0.f);
                #pragma unroll
                for (int e = 0; e < NEXP; e++) s[e] += hv * w2s[e * 128 + cc];
            }
            #pragma unroll
            for (int o = 16; o > 0; o >>= 1)
                #pragma unroll
                for (int e = 0; e < NEXP; e++)
                    s[e] += __shfl_xor_sync(0xffffffff, s[e], o);
            if (lane < NEXP)
                g_rspart[(size_t)(base + wid2) * 32 + q * 8 + lane] = s[lane];
        }
    }
}

// ---------------------------------------------------------------------------
// Launch 5: finalize — deterministic fixed-order combine, argmax, count delta
// ---------------------------------------------------------------------------
__global__ __launch_bounds__(256) void finalize_kernel(const float* __restrict__ b2) {
    int i = blockIdx.x * 256 + threadIdx.x;
    int n = g_nrefine;
    if (i >= n) return;
    int t = g_rlist[i];
    const float* p = g_rspart + (size_t)i * 32;
    float bv = -1e30f; int best = 0;
    #pragma unroll
    for (int e = 0; e < NEXP; e++) {
        float v = p[e] + p[8 + e] + p[16 + e] + p[24 + e] + b2[e];
        if (v > bv) { bv = v; best = e; }
    }
    int old = g_eid[t];
    if (best != old) {
        atomicSub(&g_cnt[old], 1);
        atomicAdd(&g_cnt[best], 1);
        g_eid[t] = best;
    }
}

// ---------------------------------------------------------------------------
// Launch 6: scatter (inline 8-wide prefix from final counts)
// ---------------------------------------------------------------------------
__global__ void scatter_kernel(int ntok) {
    int t = blockIdx.x * 256 + threadIdx.x;
    if (t >= ntok) return;
    int e = g_eid[t];
    int seg = 0;
    #pragma unroll
    for (int i = 0; i < NEXP; i++) if (i < e) seg += g_cnt[i];
    int pos = seg + atomicAdd(&g_cur[e], 1);
    g_sorted[pos] = t;
}

// ---------------------------------------------------------------------------
extern "C" void kernel_launch(void* const* d_in, const int* in_sizes, int n_in,
                              void* d_out, int out_size)
{
    const float* X  = (const float*)d_in[0];
    const float* w1 = (const float*)d_in[1];
    const float* b1 = (const float*)d_in[2];
    const float* w2 = (const float*)d_in[3];
    const float* b2 = (const float*)d_in[4];
    const float* eW = (const float*)d_in[5];
    const float* eb = (const float*)d_in[6];
    float* out = (float*)d_out;

    cudaFuncSetAttribute(mma_gemm_kernel<false, true, true>,
                         cudaFuncAttributeMaxDynamicSharedMemorySize, DYN_SMEM);
    cudaFuncSetAttribute(mma_gemm_kernel<true, false, false>,
                         cudaFuncAttributeMaxDynamicSharedMemorySize, DYN_SMEM);

    __half *xh, *w1t, *wt, *hbuf;
    cudaGetSymbolAddress((void**)&xh,   g_xh);
    cudaGetSymbolAddress((void**)&w1t,  g_w1t);
    cudaGetSymbolAddress((void**)&wt,   g_wt);
    cudaGetSymbolAddress((void**)&hbuf, g_h16);

    prep_kernel<<<8192 + 9216, 256>>>(X, w1, eW);               // launch 1
    mma_gemm_kernel<false, true, true>                          // launch 2
        <<<dim3(MD / BN, 1, NT / BM), 128, DYN_SMEM>>>(
        xh, w1t, b1, hbuf, MD, MD);
    route_pass1<<<NT / 8, 256>>>(w2, b2);                       // launch 3
    refine_kernel<<<REFG, 256>>>(X, w1, b1, w2);                // launch 4 (ncu)
    finalize_kernel<<<NT / 256, 256>>>(b2);                     // launch 5
    scatter_kernel<<<NT / 256, 256>>>(NT);                      // launch 6
    mma_gemm_kernel<true, false, false>                         // launch 7
        <<<dim3(HD / BN, NEXP, NT / BM), 128, DYN_SMEM>>>(
        xh, wt, eb, out, HD, HD);
}